// round 11
// baseline (speedup 1.0000x reference)
#include <cuda_runtime.h>
#include <cuda_bf16.h>
#include <math.h>

#define S_LEN 4096
#define NH 16
#define DK 128
#define CC 64
#define NCHUNK 64
#define NT 256
#define SPL 2
#define NTILES 2048
#define KHS 136
#define AS2 72
#define XT 72
#define UTS 72
#define RS 132

// packed bf16 scratch: [0]=hi,[1]=lo
__device__ unsigned g_kcd[2][NTILES * 4096];  // [c][dk/2]
__device__ unsigned g_qg[2][NTILES * 4096];   // [c][dk/2]
__device__ unsigned g_kdT[2][NTILES * 4096];  // [dk][c/2]
__device__ unsigned g_uT[2][NTILES * 4096];   // [dv][c/2]
__device__ unsigned g_at[2][NTILES * 2048];   // [c][j/2]
__device__ float g_egl[NTILES];

__device__ __forceinline__ void bsplit(float x, __nv_bfloat16& hi, __nv_bfloat16& lo) {
    hi = __float2bfloat16(x);
    lo = __float2bfloat16(x - __bfloat162float(hi));
}
__device__ __forceinline__ void bsplit2(float x0, float x1, unsigned& h, unsigned& l) {
    __nv_bfloat16 h0 = __float2bfloat16(x0), h1 = __float2bfloat16(x1);
    __nv_bfloat16 g0 = __float2bfloat16(x0 - __bfloat162float(h0));
    __nv_bfloat16 g1 = __float2bfloat16(x1 - __bfloat162float(h1));
    h = (unsigned)*(unsigned short*)&h0 | ((unsigned)*(unsigned short*)&h1 << 16);
    l = (unsigned)*(unsigned short*)&g0 | ((unsigned)*(unsigned short*)&g1 << 16);
}
__device__ __forceinline__ float2 upk(unsigned h, unsigned l) {
    __nv_bfloat162 a = *reinterpret_cast<__nv_bfloat162*>(&h);
    __nv_bfloat162 b = *reinterpret_cast<__nv_bfloat162*>(&l);
    return make_float2(__bfloat162float(a.x) + __bfloat162float(b.x),
                       __bfloat162float(a.y) + __bfloat162float(b.y));
}
__device__ __forceinline__ unsigned sm_addr(const void* p) {
    return (unsigned)__cvta_generic_to_shared(p);
}
__device__ __forceinline__ void ldsm4(unsigned* r, unsigned a) {
    asm volatile("ldmatrix.sync.aligned.m8n8.x4.shared.b16 {%0,%1,%2,%3}, [%4];"
                 : "=r"(r[0]), "=r"(r[1]), "=r"(r[2]), "=r"(r[3]) : "r"(a));
}
__device__ __forceinline__ void ldsm2(unsigned* r, unsigned a) {
    asm volatile("ldmatrix.sync.aligned.m8n8.x2.shared.b16 {%0,%1}, [%2];"
                 : "=r"(r[0]), "=r"(r[1]) : "r"(a));
}
__device__ __forceinline__ void mma16816(float* d, unsigned a0, unsigned a1,
                                         unsigned a2, unsigned a3,
                                         unsigned b0, unsigned b1) {
    asm volatile("mma.sync.aligned.m16n8k16.row.col.f32.bf16.bf16.f32 "
                 "{%0,%1,%2,%3}, {%4,%5,%6,%7}, {%8,%9}, {%0,%1,%2,%3};\n"
                 : "+f"(d[0]), "+f"(d[1]), "+f"(d[2]), "+f"(d[3])
                 : "r"(a0), "r"(a1), "r"(a2), "r"(a3), "r"(b0), "r"(b1));
}
__device__ __forceinline__ void mma_p3(float* d, const unsigned* ah, const unsigned* al,
                                       unsigned bh0, unsigned bh1,
                                       unsigned bl0, unsigned bl1) {
    mma16816(d, ah[0], ah[1], ah[2], ah[3], bh0, bh1);
    mma16816(d, ah[0], ah[1], ah[2], ah[3], bl0, bl1);
    mma16816(d, al[0], al[1], al[2], al[3], bh0, bh1);
}
__device__ __forceinline__ void cpa16(void* dst, const void* src) {
    unsigned d = (unsigned)__cvta_generic_to_shared(dst);
    asm volatile("cp.async.cg.shared.global [%0], [%1], 16;\n" :: "r"(d), "l"(src));
}

// ======================= kernel 1: prep =======================
struct __align__(16) SmemP {
    float rhs[CC * RS];
    float gst[CC], bst[CC], egc[CC], iegc[CC], kdec[CC], kw[CC], negbe[CC];
    __nv_bfloat16 khi[CC * KHS], klo[CC * KHS], qhi[CC * KHS], qlo[CC * KHS];
    __nv_bfloat16 abh[CC * AS2], abl[CC * AS2];
    __nv_bfloat16 xth[DK * XT], xtl[DK * XT];
    __nv_bfloat16 rbh[DK * 24], rbl[DK * 24];
};

// solve (I-A)X=rhs[64][128]; X -> rhs fp32, X^T -> xth/xtl bf16
__device__ __forceinline__ void solve_pass(SmemP& sm, int tid, int warp, int gq_,
                                           int tig, int lr, int lc8, int lr2, int lc2) {
    if (tid < 128) {
        int dv = tid;
#pragma unroll
        for (int rp = 0; rp < 8; ++rp) {
            unsigned hh, ll;
            bsplit2(sm.rhs[(2 * rp) * RS + dv], sm.rhs[(2 * rp + 1) * RS + dv], hh, ll);
            *(unsigned*)&sm.rbh[dv * 24 + 2 * rp] = hh;
            *(unsigned*)&sm.rbl[dv * 24 + 2 * rp] = ll;
        }
    }
    __syncthreads();
    for (int blk = 0; blk < 4; ++blk) {
        const int i0 = blk * 16, n0 = warp * 16;
        if (blk > 0) {
            float acc[2][4] = {};
            unsigned aAh = sm_addr(&sm.abh[(i0 + lr) * AS2 + lc8]);
            unsigned aAl = sm_addr(&sm.abl[(i0 + lr) * AS2 + lc8]);
            for (int ks = 0; ks < blk; ++ks) {
                unsigned ah[4], al[4];
                ldsm4(ah, aAh + ks * 32); ldsm4(al, aAl + ks * 32);
#pragma unroll
                for (int s = 0; s < 2; ++s) {
                    unsigned bh2[2], bl2[2];
                    ldsm2(bh2, sm_addr(&sm.xth[(n0 + s * 8 + lr2) * XT + ks * 16 + lc2]));
                    ldsm2(bl2, sm_addr(&sm.xtl[(n0 + s * 8 + lr2) * XT + ks * 16 + lc2]));
                    mma_p3(acc[s], ah, al, bh2[0], bh2[1], bl2[0], bl2[1]);
                }
            }
#pragma unroll
            for (int s = 0; s < 2; ++s)
#pragma unroll
                for (int e = 0; e < 4; ++e) {
                    int i = i0 + gq_ + ((e >> 1) << 3), w = n0 + s * 8 + 2 * tig + (e & 1);
                    float r = sm.rhs[i * RS + w] + acc[s][e];
                    __nv_bfloat16 hi, lo; bsplit(r, hi, lo);
                    sm.rbh[w * 24 + (i - i0)] = hi;
                    sm.rbl[w * 24 + (i - i0)] = lo;
                }
            __syncthreads();
        }
        {
            unsigned ah[4], al[4];
            ldsm4(ah, sm_addr(&sm.abh[(i0 + lr) * AS2 + i0 + lc8]));
            ldsm4(al, sm_addr(&sm.abl[(i0 + lr) * AS2 + i0 + lc8]));
            float acc[2][4] = {};
#pragma unroll
            for (int s = 0; s < 2; ++s) {
                unsigned bh2[2], bl2[2];
                ldsm2(bh2, sm_addr(&sm.rbh[(n0 + s * 8 + lr2) * 24 + lc2]));
                ldsm2(bl2, sm_addr(&sm.rbl[(n0 + s * 8 + lr2) * 24 + lc2]));
                mma_p3(acc[s], ah, al, bh2[0], bh2[1], bl2[0], bl2[1]);
            }
#pragma unroll
            for (int s = 0; s < 2; ++s)
#pragma unroll
                for (int e = 0; e < 4; ++e) {
                    int i = i0 + gq_ + ((e >> 1) << 3), w = n0 + s * 8 + 2 * tig + (e & 1);
                    sm.rhs[i * RS + w] = acc[s][e];
                    __nv_bfloat16 hi, lo; bsplit(acc[s][e], hi, lo);
                    sm.xth[w * XT + i] = hi;
                    sm.xtl[w * XT + i] = lo;
                }
        }
        __syncthreads();
    }
}

__global__ __launch_bounds__(NT, 1)
void gdn_prep(const float* __restrict__ gq, const float* __restrict__ gk,
              const float* __restrict__ gv, const float* __restrict__ gg,
              const float* __restrict__ gb) {
    extern __shared__ char smraw[];
    SmemP& sm = *reinterpret_cast<SmemP*>(smraw);
    const int tile = blockIdx.x, bh = tile / NCHUNK, n = tile % NCHUNK;
    const int b = bh / NH, h = bh % NH, s0 = n * CC;
    const int tid = threadIdx.x, warp = tid >> 5, lane = tid & 31;
    const int gq_ = lane >> 2, tig = lane & 3;
    const int lr = lane & 15, lc8 = (lane >> 4) << 3;
    const int lr2 = lane & 7, lc2 = ((lane >> 3) & 1) << 3;
    const unsigned tb4 = tile * 4096u, tb2 = tile * 2048u;
    const float QSCALE = 0.08838834764831845f;

    if (tid < CC) {
        size_t gi = ((size_t)b * S_LEN + s0 + tid) * NH + h;
        sm.gst[tid] = gg[gi];
        sm.bst[tid] = gb[gi];
    }
    __syncthreads();
    if (warp == 0) {
        float a0 = sm.gst[lane], a1 = sm.gst[lane + 32];
#pragma unroll
        for (int o = 1; o < 32; o <<= 1) {
            float t = __shfl_up_sync(0xffffffffu, a0, o);
            if (lane >= o) a0 += t;
        }
        float tot0 = __shfl_sync(0xffffffffu, a0, 31);
#pragma unroll
        for (int o = 1; o < 32; o <<= 1) {
            float t = __shfl_up_sync(0xffffffffu, a1, o);
            if (lane >= o) a1 += t;
        }
        a1 += tot0;
        float glast = __shfl_sync(0xffffffffu, a1, 31);
        float e0 = expf(a0), e1 = expf(a1);
        sm.egc[lane] = e0;                sm.egc[lane + 32] = e1;
        sm.iegc[lane] = expf(-a0);        sm.iegc[lane + 32] = expf(-a1);
        sm.kdec[lane] = expf(glast - a0); sm.kdec[lane + 32] = expf(glast - a1);
        float b0 = sm.bst[lane], b1 = sm.bst[lane + 32];
        sm.kw[lane] = b0 * e0;            sm.kw[lane + 32] = b1 * e1;
        sm.negbe[lane] = -b0 * e0;        sm.negbe[lane + 32] = -b1 * e1;
        if (lane == 0) g_egl[tile] = expf(glast);   // FIX for R8 NaN
    } else {   // v raw -> rhs
        for (int i = tid - 32; i < CC * 32; i += NT - 32) {
            int r = i >> 5, c4 = (i & 31) * 4;
            size_t rowb = (((size_t)b * S_LEN + s0 + r) * NH + h) * (size_t)DK;
            *(float4*)&sm.rhs[r * RS + c4] = *(const float4*)(gv + rowb + c4);
        }
    }
    __syncthreads();
    // norm+split k,qg ; qg also to global
#pragma unroll
    for (int it = 0; it < 4; ++it) {
        int r = warp + it * 16, r2 = r + 8;
#pragma unroll
        for (int pp = 0; pp < 2; ++pp) {
            int rr = pp ? r2 : r;
            size_t rb = (((size_t)b * S_LEN + s0 + rr) * NH + h) * (size_t)DK + lane * 4;
            float4 qv = *(const float4*)(gq + rb);
            float4 kv = *(const float4*)(gk + rb);
            float sq = qv.x*qv.x + qv.y*qv.y + qv.z*qv.z + qv.w*qv.w;
            float sk = kv.x*kv.x + kv.y*kv.y + kv.z*kv.z + kv.w*kv.w;
#pragma unroll
            for (int o = 16; o > 0; o >>= 1) {
                sq += __shfl_xor_sync(0xffffffffu, sq, o);
                sk += __shfl_xor_sync(0xffffffffu, sk, o);
            }
            float rqs = rsqrtf(sq + 1e-6f) * QSCALE * sm.egc[rr];
            float rks = rsqrtf(sk + 1e-6f);
            int c4 = lane * 4;
            unsigned hh, ll;
            bsplit2(kv.x * rks, kv.y * rks, hh, ll);
            *(unsigned*)&sm.khi[rr*KHS + c4] = hh; *(unsigned*)&sm.klo[rr*KHS + c4] = ll;
            bsplit2(kv.z * rks, kv.w * rks, hh, ll);
            *(unsigned*)&sm.khi[rr*KHS + c4+2] = hh; *(unsigned*)&sm.klo[rr*KHS + c4+2] = ll;
            bsplit2(qv.x * rqs, qv.y * rqs, hh, ll);
            *(unsigned*)&sm.qhi[rr*KHS + c4] = hh; *(unsigned*)&sm.qlo[rr*KHS + c4] = ll;
            g_qg[0][tb4 + rr * 64 + lane * 2] = hh;
            g_qg[1][tb4 + rr * 64 + lane * 2] = ll;
            bsplit2(qv.z * rqs, qv.w * rqs, hh, ll);
            *(unsigned*)&sm.qhi[rr*KHS + c4+2] = hh; *(unsigned*)&sm.qlo[rr*KHS + c4+2] = ll;
            g_qg[0][tb4 + rr * 64 + lane * 2 + 1] = hh;
            g_qg[1][tb4 + rr * 64 + lane * 2 + 1] = ll;
        }
    }
    for (int i = tid; i < CC * 32; i += NT) {   // rhs *= beta
        int r = i >> 5, c4 = (i & 31) * 4;
        float bt = sm.bst[r];
        float4 t = *(float4*)&sm.rhs[r * RS + c4];
        t.x *= bt; t.y *= bt; t.z *= bt; t.w *= bt;
        *(float4*)&sm.rhs[r * RS + c4] = t;
    }
    __syncthreads();

    // Grams: A -> smem; attn -> global
    {
        const int m0 = (warp >> 1) * 16, n0 = (warp & 1) * 32;
        float accG[4][4] = {}, accQ[4][4] = {};
        if (m0 + 15 >= n0) {
            unsigned aKh = sm_addr(&sm.khi[(m0+lr)*KHS + lc8]);
            unsigned aKl = sm_addr(&sm.klo[(m0+lr)*KHS + lc8]);
            unsigned aQh = sm_addr(&sm.qhi[(m0+lr)*KHS + lc8]);
            unsigned aQl = sm_addr(&sm.qlo[(m0+lr)*KHS + lc8]);
            unsigned b0a = sm_addr(&sm.khi[(n0+lr)*KHS + lc8]);
            unsigned b0b = sm_addr(&sm.klo[(n0+lr)*KHS + lc8]);
            unsigned b1a = sm_addr(&sm.khi[(n0+16+lr)*KHS + lc8]);
            unsigned b1b = sm_addr(&sm.klo[(n0+16+lr)*KHS + lc8]);
            const bool d1 = (m0+15 >= n0+8), d2 = (m0+15 >= n0+16), d3 = (m0+15 >= n0+24);
            for (int k0 = 0; k0 < DK; k0 += 16) {
                unsigned kh[4], kl[4], qh[4], ql[4], p0h[4], p0l[4];
                ldsm4(kh, aKh + k0*2); ldsm4(kl, aKl + k0*2);
                ldsm4(qh, aQh + k0*2); ldsm4(ql, aQl + k0*2);
                ldsm4(p0h, b0a + k0*2); ldsm4(p0l, b0b + k0*2);
                mma_p3(accG[0], kh, kl, p0h[0], p0h[2], p0l[0], p0l[2]);
                mma_p3(accQ[0], qh, ql, p0h[0], p0h[2], p0l[0], p0l[2]);
                if (d1) {
                    mma_p3(accG[1], kh, kl, p0h[1], p0h[3], p0l[1], p0l[3]);
                    mma_p3(accQ[1], qh, ql, p0h[1], p0h[3], p0l[1], p0l[3]);
                }
                if (d2) {
                    unsigned p1h[4], p1l[4];
                    ldsm4(p1h, b1a + k0*2); ldsm4(p1l, b1b + k0*2);
                    mma_p3(accG[2], kh, kl, p1h[0], p1h[2], p1l[0], p1l[2]);
                    mma_p3(accQ[2], qh, ql, p1h[0], p1h[2], p1l[0], p1l[2]);
                    if (d3) {
                        mma_p3(accG[3], kh, kl, p1h[1], p1h[3], p1l[1], p1l[3]);
                        mma_p3(accQ[3], qh, ql, p1h[1], p1h[3], p1l[1], p1l[3]);
                    }
                }
            }
        }
#pragma unroll
        for (int nt = 0; nt < 4; ++nt) {
            int j0 = n0 + nt * 8 + 2 * tig;
            float ie0 = sm.iegc[j0], ie1 = sm.iegc[j0 + 1];
#pragma unroll
            for (int rh = 0; rh < 2; ++rh) {
                int i = m0 + gq_ + rh * 8;
                float nb = sm.negbe[i];
                float av0 = (i > j0)      ? nb * ie0 * accG[nt][rh*2]   : 0.f;
                float av1 = (i > j0 + 1)  ? nb * ie1 * accG[nt][rh*2+1] : 0.f;
                float at0 = (i >= j0)     ? accQ[nt][rh*2]   * ie0 : 0.f;
                float at1 = (i >= j0 + 1) ? accQ[nt][rh*2+1] * ie1 : 0.f;
                unsigned hh, ll;
                bsplit2(av0, av1, hh, ll);
                *(unsigned*)&sm.abh[i*AS2 + j0] = hh;
                *(unsigned*)&sm.abl[i*AS2 + j0] = ll;
                bsplit2(at0, at1, hh, ll);
                g_at[0][tb2 + i * 32 + (j0 >> 1)] = hh;
                g_at[1][tb2 + i * 32 + (j0 >> 1)] = ll;
            }
        }
    }
    __syncthreads();
    // invert diag blocks (warps 0-3); kdT store (warps 4-7)
    if (warp < 4) {
        const int r0 = warp * 16;
        if (lane < 16) {
            float x[16];
#pragma unroll
            for (int r = 0; r < 16; ++r) {
                float acc = (r == lane) ? 1.f : 0.f;
#pragma unroll
                for (int j = 0; j < 16; ++j)
                    if (j < r) {
                        float a = __bfloat162float(sm.abh[(r0+r)*AS2 + r0+j]) +
                                  __bfloat162float(sm.abl[(r0+r)*AS2 + r0+j]);
                        acc += a * x[j];
                    }
                x[r] = acc;
            }
            __syncwarp(0x0000ffffu);
#pragma unroll
            for (int r = 0; r < 16; ++r) {
                __nv_bfloat16 hi, lo; bsplit(x[r], hi, lo);
                sm.abh[(r0+r)*AS2 + r0 + lane] = hi;
                sm.abl[(r0+r)*AS2 + r0 + lane] = lo;
            }
        }
    } else {
        int t = (warp - 4) * 32 + lane;
        for (int w = t; w < 4096; w += 128) {
            int dk = w >> 5, c0 = (w & 31) * 2;
            float v0 = (__bfloat162float(sm.khi[c0*KHS + dk]) +
                        __bfloat162float(sm.klo[c0*KHS + dk])) * sm.kdec[c0];
            float v1 = (__bfloat162float(sm.khi[(c0+1)*KHS + dk]) +
                        __bfloat162float(sm.klo[(c0+1)*KHS + dk])) * sm.kdec[c0 + 1];
            unsigned hh, ll; bsplit2(v0, v1, hh, ll);
            g_kdT[0][tb4 + w] = hh;
            g_kdT[1][tb4 + w] = ll;
        }
    }
    __syncthreads();
    solve_pass(sm, tid, warp, gq_, tig, lr, lc8, lr2, lc2);   // X = u
    for (int w = tid; w < 4096; w += NT) {   // uT out
        int dv = w >> 5, cp = w & 31;
        g_uT[0][tb4 + w] = *(unsigned*)&sm.xth[dv * XT + 2 * cp];
        g_uT[1][tb4 + w] = *(unsigned*)&sm.xtl[dv * XT + 2 * cp];
    }
    for (int i = tid; i < CC * 32; i += NT) {   // rhs = kw * k
        int c = i >> 5, d4 = (i & 31) * 4;
        float kwv = sm.kw[c];
#pragma unroll
        for (int t = 0; t < 4; ++t)
            sm.rhs[c * RS + d4 + t] =
                (__bfloat162float(sm.khi[c*KHS + d4 + t]) +
                 __bfloat162float(sm.klo[c*KHS + d4 + t])) * kwv;
    }
    __syncthreads();
    solve_pass(sm, tid, warp, gq_, tig, lr, lc8, lr2, lc2);   // X = kcd
    for (int w = tid; w < 4096; w += NT) {
        int c = w >> 6, dp = w & 63;
        unsigned hh, ll;
        bsplit2(sm.rhs[c * RS + 2 * dp], sm.rhs[c * RS + 2 * dp + 1], hh, ll);
        g_kcd[0][tb4 + w] = hh;
        g_kcd[1][tb4 + w] = ll;
    }
}

// ======================= kernel 2: scan =======================
struct __align__(16) SmemS {
    __nv_bfloat16 sh[64 * KHS], sl[64 * KHS];
    __nv_bfloat16 kch[64 * KHS], kcl[64 * KHS];
    __nv_bfloat16 qgh[64 * KHS], qgl[64 * KHS];
    __nv_bfloat16 uth[64 * UTS], utl[64 * UTS];
    __nv_bfloat16 ath[64 * UTS], atl[64 * UTS];
    __nv_bfloat16 kth[128 * UTS], ktl[128 * UTS];
    __nv_bfloat16 vnh[64 * UTS], vnl[64 * UTS];
};

__global__ __launch_bounds__(NT, 1)
void gdn_scan(float* __restrict__ gout) {
    extern __shared__ char smraw[];
    SmemS& s = *reinterpret_cast<SmemS*>(smraw);
    const int bh = blockIdx.x >> 1, split = blockIdx.x & 1;
    const int b = bh / NH, h = bh % NH;
    const int tid = threadIdx.x, warp = tid >> 5, lane = tid & 31;
    const int gq_ = lane >> 2, tig = lane & 3;
    const int lr = lane & 15, lc8 = (lane >> 4) << 3;
    const int m0 = (warp >> 1) * 16, n0 = (warp & 1) * 32;

    const __nv_bfloat16 bz = __float2bfloat16(0.f);
    for (int i = tid; i < 64 * KHS; i += NT) { s.sh[i] = bz; s.sl[i] = bz; }

#define CP_A(tl) do { unsigned t4 = (unsigned)(tl) * 4096u; \
    for (int i = tid; i < 1024; i += NT) { int r = i >> 4, j = i & 15; \
        cpa16(&s.kch[r*KHS + j*8], &g_kcd[0][t4 + r*64 + j*4]); \
        cpa16(&s.kcl[r*KHS + j*8], &g_kcd[1][t4 + r*64 + j*4]); } \
    for (int i = tid; i < 512; i += NT) { int r = i >> 3, j = i & 7; \
        unsigned sw = t4 + (split*64 + r)*32 + j*4; \
        cpa16(&s.uth[r*UTS + j*8], &g_uT[0][sw]); \
        cpa16(&s.utl[r*UTS + j*8], &g_uT[1][sw]); } \
    asm volatile("cp.async.commit_group;\n"); } while (0)
#define CP_B(tl) do { unsigned t4 = (unsigned)(tl) * 4096u, t2 = (unsigned)(tl) * 2048u; \
    for (int i = tid; i < 1024; i += NT) { int r = i >> 4, j = i & 15; \
        cpa16(&s.qgh[r*KHS + j*8], &g_qg[0][t4 + r*64 + j*4]); \
        cpa16(&s.qgl[r*KHS + j*8], &g_qg[1][t4 + r*64 + j*4]); } \
    for (int i = tid; i < 512; i += NT) { int r = i >> 3, j = i & 7; \
        cpa16(&s.ath[r*UTS + j*8], &g_at[0][t2 + r*32 + j*4]); \
        cpa16(&s.atl[r*UTS + j*8], &g_at[1][t2 + r*32 + j*4]); } \
    for (int i = tid; i < 1024; i += NT) { int r = i >> 3, j = i & 7; \
        cpa16(&s.kth[r*UTS + j*8], &g_kdT[0][t4 + r*32 + j*4]); \
        cpa16(&s.ktl[r*UTS + j*8], &g_kdT[1][t4 + r*32 + j*4]); } \
    asm volatile("cp.async.commit_group;\n"); } while (0)

    int tile0 = bh * NCHUNK;
    CP_A(tile0); CP_B(tile0);

    for (int n = 0; n < NCHUNK; ++n) {
        const int tile = tile0 + n, s0 = n * CC;
        asm volatile("cp.async.wait_group 1;\n");
        __syncthreads();
        float egl = g_egl[tile];

        // P-A: vn^T = uT - S^T @ kcd^T
        {
            float acc[4][4] = {};
            unsigned aSh = sm_addr(&s.sh[(m0+lr)*KHS + lc8]);
            unsigned aSl = sm_addr(&s.sl[(m0+lr)*KHS + lc8]);
            unsigned b0a = sm_addr(&s.kch[(n0+lr)*KHS + lc8]);
            unsigned b0b = sm_addr(&s.kcl[(n0+lr)*KHS + lc8]);
            unsigned b1a = sm_addr(&s.kch[(n0+16+lr)*KHS + lc8]);
            unsigned b1b = sm_addr(&s.kcl[(n0+16+lr)*KHS + lc8]);
            for (int k0 = 0; k0 < DK; k0 += 16) {
                unsigned ah[4], al[4], p0h[4], p0l[4], p1h[4], p1l[4];
                ldsm4(ah, aSh + k0*2); ldsm4(al, aSl + k0*2);
                ldsm4(p0h, b0a + k0*2); ldsm4(p0l, b0b + k0*2);
                ldsm4(p1h, b1a + k0*2); ldsm4(p1l, b1b + k0*2);
                mma_p3(acc[0], ah, al, p0h[0], p0h[2], p0l[0], p0l[2]);
                mma_p3(acc[1], ah, al, p0h[1], p0h[3], p0l[1], p0l[3]);
                mma_p3(acc[2], ah, al, p1h[0], p1h[2], p1l[0], p1l[2]);
                mma_p3(acc[3], ah, al, p1h[1], p1h[3], p1l[1], p1l[3]);
            }
#pragma unroll
            for (int nt = 0; nt < 4; ++nt)
#pragma unroll
                for (int rh = 0; rh < 2; ++rh) {
                    int dv = m0 + gq_ + rh * 8, c0 = n0 + nt * 8 + 2 * tig;
                    float2 u = upk(*(unsigned*)&s.uth[dv*UTS + c0],
                                   *(unsigned*)&s.utl[dv*UTS + c0]);
                    unsigned hh, ll;
                    bsplit2(u.x - acc[nt][rh*2], u.y - acc[nt][rh*2+1], hh, ll);
                    *(unsigned*)&s.vnh[dv*UTS + c0] = hh;
                    *(unsigned*)&s.vnl[dv*UTS + c0] = ll;
                }
        }
        __syncthreads();
        if (n + 1 < NCHUNK) { CP_A(tile + 1); asm volatile("cp.async.wait_group 1;\n"); }
        else asm volatile("cp.async.wait_group 0;\n");
        __syncthreads();

        // P-B: out^T = S^T@qg^T + vn^T@attn^T
        {
            float acc[4][4] = {};
            unsigned aSh = sm_addr(&s.sh[(m0+lr)*KHS + lc8]);
            unsigned aSl = sm_addr(&s.sl[(m0+lr)*KHS + lc8]);
            unsigned b0a = sm_addr(&s.qgh[(n0+lr)*KHS + lc8]);
            unsigned b0b = sm_addr(&s.qgl[(n0+lr)*KHS + lc8]);
            unsigned b1a = sm_addr(&s.qgh[(n0+16+lr)*KHS + lc8]);
            unsigned b1b = sm_addr(&s.qgl[(n0+16+lr)*KHS + lc8]);
            for (int k0 = 0; k0 < DK; k0 += 16) {
                unsigned ah[4], al[4], p0h[4], p0l[4], p1h[4], p1l[4];
                ldsm4(ah, aSh + k0*2); ldsm4(al, aSl + k0*2);
                ldsm4(p0h, b0a + k0*2); ldsm4(p0l, b0b + k0*2);
                ldsm4(p1h, b1a + k0*2); ldsm4(p1l, b1b + k0*2);
                mma_p3(acc[0], ah, al, p0h[0], p0h[2], p0l[0], p0l[2]);
                mma_p3(acc[1], ah, al, p0h[1], p0h[3], p0l[1], p0l[3]);
                mma_p3(acc[2], ah, al, p1h[0], p1h[2], p1l[0], p1l[2]);
                mma_p3(acc[3], ah, al, p1h[1], p1h[3], p1l[1], p1l[3]);
            }
            unsigned aVh = sm_addr(&s.vnh[(m0+lr)*UTS + lc8]);
            unsigned aVl = sm_addr(&s.vnl[(m0+lr)*UTS + lc8]);
            unsigned c0a = sm_addr(&s.ath[(n0+lr)*UTS + lc8]);
            unsigned c0b = sm_addr(&s.atl[(n0+lr)*UTS + lc8]);
            unsigned c1a = sm_addr(&s.ath[(n0+16+lr)*UTS + lc8]);
            unsigned c1b = sm_addr(&s.atl[(n0+16+lr)*UTS + lc8]);
            for (int k0 = 0; k0 < CC; k0 += 16) {
                unsigned ah[4], al[4], p0h[4], p0l[4], p1h[4], p1l[4];
                ldsm4(ah, aVh + k0*2); ldsm4(al, aVl + k0*2);
                ldsm4(p0h, c0a + k0*2); ldsm4(p0l, c0b + k0*2);
                ldsm4(p1h, c1a + k0*2); ldsm4(p1l, c1b + k0*2);
                mma_p3(acc[0], ah, al, p0h[0], p0h[2], p0l[0], p0l[2]);
                mma_p3(acc[1], ah, al, p0h[1], p0h[3], p0l[1], p0l[3]);
                mma_p3(acc[2], ah, al, p1h[0], p1h[2], p1l[0], p1l[2]);
                mma_p3(acc[3], ah, al, p1h[1], p1h[3], p1l[1], p1l[3]);
            }
#pragma unroll
            for (int nt = 0; nt < 4; ++nt)
#pragma unroll
                for (int e = 0; e < 4; ++e) {
                    int dv = m0 + gq_ + ((e >> 1) << 3);
                    int c = n0 + nt * 8 + 2 * tig + (e & 1);
                    gout[(((size_t)b * S_LEN + s0 + c) * NH + h) * (size_t)DK +
                         split * 64 + dv] = acc[nt][e];
                }
        }

        // P-C: S^T = egl*S^T + vn^T @ kdT^T
        {
            const int nn0 = (warp & 1) * 64;
            float acc[8][4] = {};
            unsigned aVh = sm_addr(&s.vnh[(m0+lr)*UTS + lc8]);
            unsigned aVl = sm_addr(&s.vnl[(m0+lr)*UTS + lc8]);
            for (int k0 = 0; k0 < CC; k0 += 16) {
                unsigned ah[4], al[4];
                ldsm4(ah, aVh + k0*2); ldsm4(al, aVl + k0*2);
#pragma unroll
                for (int p = 0; p < 4; ++p) {
                    unsigned pbh[4], pbl[4];
                    ldsm4(pbh, sm_addr(&s.kth[(nn0 + p*16 + lr)*UTS + lc8]) + k0*2);
                    ldsm4(pbl, sm_addr(&s.ktl[(nn0 + p*16 + lr)*UTS + lc8]) + k0*2);
                    mma_p3(acc[2*p],   ah, al, pbh[0], pbh[2], pbl[0], pbl[2]);
                    mma_p3(acc[2*p+1], ah, al, pbh[1], pbh[3], pbl[1], pbl[3]);
                }
            }
            __syncthreads();
#pragma unroll
            for (int nt = 0; nt < 8; ++nt)
#pragma unroll
                for (int rh = 0; rh < 2; ++rh) {
                    int dv = m0 + gq_ + rh * 8, dk0 = nn0 + nt * 8 + 2 * tig;
                    float2 so = upk(*(unsigned*)&s.sh[dv*KHS + dk0],
                                    *(unsigned*)&s.sl[dv*KHS + dk0]);
                    unsigned hh, ll;
                    bsplit2(so.x * egl + acc[nt][rh*2],
                            so.y * egl + acc[nt][rh*2+1], hh, ll);
                    *(unsigned*)&s.sh[dv*KHS + dk0] = hh;
                    *(unsigned*)&s.sl[dv*KHS + dk0] = ll;
                }
        }
        if (n + 1 < NCHUNK) CP_B(tile + 1);
    }
}

extern "C" void kernel_launch(void* const* d_in, const int* in_sizes, int n_in,
                              void* d_out, int out_size) {
    const float* q = (const float*)d_in[0];
    const float* k = (const float*)d_in[1];
    const float* v = (const float*)d_in[2];
    const float* g = (const float*)d_in[3];
    const float* beta = (const float*)d_in[4];
    float* out = (float*)d_out;
    int B = in_sizes[0] / (S_LEN * NH * DK);
    if (B < 1) B = 1;
    cudaFuncSetAttribute(gdn_prep, cudaFuncAttributeMaxDynamicSharedMemorySize,
                         (int)sizeof(SmemP));
    cudaFuncSetAttribute(gdn_scan, cudaFuncAttributeMaxDynamicSharedMemorySize,
                         (int)sizeof(SmemS));
    gdn_prep<<<B * NH * NCHUNK, NT, sizeof(SmemP)>>>(q, k, v, g, beta);
    gdn_scan<<<B * NH * SPL, NT, sizeof(SmemS)>>>(out);
}

// round 12
// speedup vs baseline: 1.6505x; 1.6505x over previous
#include <cuda_runtime.h>
#include <cuda_bf16.h>
#include <math.h>

#define S_LEN 4096
#define NH 16
#define DK 128
#define DV 128
#define CC 64
#define NCHUNK 64
#define NT 256
#define SPLIT 4
#define DVS 32
#define NTILES 2048
#define KHS 136
#define AS2 72
#define VS 36
#define VTS 72

// packed bf16 pair scratch ([0]=hi,[1]=lo)
__device__ unsigned g_k[2][NTILES * 4096];   // [c][dk pair]
__device__ unsigned g_qg[2][NTILES * 4096];  // [c][dk pair]
__device__ unsigned g_ab[2][NTILES * 2048];  // [i][j pair]  (A strict-lower, Ti diag)
__device__ unsigned g_at[2][NTILES * 2048];  // [i][j pair]  (attn masked)
__device__ float g_sc[NTILES * 256];         // kw[64], kdec[64], beta[64], egl

__device__ __forceinline__ void bsplit(float x, __nv_bfloat16& hi, __nv_bfloat16& lo) {
    hi = __float2bfloat16(x);
    lo = __float2bfloat16(x - __bfloat162float(hi));
}
__device__ __forceinline__ void bsplit2(float x0, float x1, unsigned& h, unsigned& l) {
    __nv_bfloat16 h0 = __float2bfloat16(x0), h1 = __float2bfloat16(x1);
    __nv_bfloat16 g0 = __float2bfloat16(x0 - __bfloat162float(h0));
    __nv_bfloat16 g1 = __float2bfloat16(x1 - __bfloat162float(h1));
    h = (unsigned)*(unsigned short*)&h0 | ((unsigned)*(unsigned short*)&h1 << 16);
    l = (unsigned)*(unsigned short*)&g0 | ((unsigned)*(unsigned short*)&g1 << 16);
}
__device__ __forceinline__ unsigned sm_addr(const void* p) {
    return (unsigned)__cvta_generic_to_shared(p);
}
__device__ __forceinline__ void ldsm4(unsigned* r, unsigned a) {
    asm volatile("ldmatrix.sync.aligned.m8n8.x4.shared.b16 {%0,%1,%2,%3}, [%4];"
                 : "=r"(r[0]), "=r"(r[1]), "=r"(r[2]), "=r"(r[3]) : "r"(a));
}
__device__ __forceinline__ void ldsm2(unsigned* r, unsigned a) {
    asm volatile("ldmatrix.sync.aligned.m8n8.x2.shared.b16 {%0,%1}, [%2];"
                 : "=r"(r[0]), "=r"(r[1]) : "r"(a));
}
__device__ __forceinline__ void mma16816(float* d, unsigned a0, unsigned a1,
                                         unsigned a2, unsigned a3,
                                         unsigned b0, unsigned b1) {
    asm volatile("mma.sync.aligned.m16n8k16.row.col.f32.bf16.bf16.f32 "
                 "{%0,%1,%2,%3}, {%4,%5,%6,%7}, {%8,%9}, {%0,%1,%2,%3};\n"
                 : "+f"(d[0]), "+f"(d[1]), "+f"(d[2]), "+f"(d[3])
                 : "r"(a0), "r"(a1), "r"(a2), "r"(a3), "r"(b0), "r"(b1));
}
__device__ __forceinline__ void mma_p3(float* d, const unsigned* ah, const unsigned* al,
                                       unsigned bh0, unsigned bh1,
                                       unsigned bl0, unsigned bl1) {
    mma16816(d, ah[0], ah[1], ah[2], ah[3], bh0, bh1);
    mma16816(d, ah[0], ah[1], ah[2], ah[3], bl0, bl1);
    mma16816(d, al[0], al[1], al[2], al[3], bh0, bh1);
}
__device__ __forceinline__ void ldBtrans(const __nv_bfloat16* p, int stride, int n,
                                         int k0, int tig, unsigned* bb) {
    const unsigned short* s = reinterpret_cast<const unsigned short*>(p);
    int r = k0 + 2 * tig;
    unsigned l0 = s[r * stride + n], h0 = s[(r + 1) * stride + n];
    unsigned l1 = s[(r + 8) * stride + n], h1 = s[(r + 9) * stride + n];
    bb[0] = l0 | (h0 << 16);
    bb[1] = l1 | (h1 << 16);
}
__device__ __forceinline__ void cpa16(void* dst, const void* src) {
    unsigned d = (unsigned)__cvta_generic_to_shared(dst);
    asm volatile("cp.async.cg.shared.global [%0], [%1], 16;\n" :: "r"(d), "l"(src));
}

// ===================== kernel 1: prep (validated R9, unchanged) =====================
struct __align__(16) SmemP {
    float gst[CC], bst[CC], egc[CC], iegc[CC], kdec[CC], kw[CC], negbe[CC];
    __nv_bfloat16 khi[CC * KHS], klo[CC * KHS], qhi[CC * KHS], qlo[CC * KHS];
    __nv_bfloat16 abh[CC * AS2], abl[CC * AS2];
};

__global__ __launch_bounds__(NT, 2)
void gdn_prep(const float* __restrict__ gq, const float* __restrict__ gk,
              const float* __restrict__ gg, const float* __restrict__ gb) {
    extern __shared__ char smraw[];
    SmemP& sm = *reinterpret_cast<SmemP*>(smraw);
    const int tile = blockIdx.x, bh = tile / NCHUNK, n = tile % NCHUNK;
    const int b = bh / NH, h = bh % NH, s0 = n * CC;
    const int tid = threadIdx.x, warp = tid >> 5, lane = tid & 31;
    const int gq_ = lane >> 2, tig = lane & 3;
    const int lr = lane & 15, lc8 = (lane >> 4) << 3;
    const unsigned t4 = (unsigned)tile * 4096u, t2 = (unsigned)tile * 2048u;
    const float QSCALE = 0.08838834764831845f;

    if (tid < CC) {
        size_t gi = ((size_t)b * S_LEN + s0 + tid) * NH + h;
        sm.gst[tid] = gg[gi];
        sm.bst[tid] = gb[gi];
    }
    __syncthreads();
    if (warp == 0) {
        float a0 = sm.gst[lane], a1 = sm.gst[lane + 32];
#pragma unroll
        for (int o = 1; o < 32; o <<= 1) {
            float t = __shfl_up_sync(0xffffffffu, a0, o);
            if (lane >= o) a0 += t;
        }
        float tot0 = __shfl_sync(0xffffffffu, a0, 31);
#pragma unroll
        for (int o = 1; o < 32; o <<= 1) {
            float t = __shfl_up_sync(0xffffffffu, a1, o);
            if (lane >= o) a1 += t;
        }
        a1 += tot0;
        float glast = __shfl_sync(0xffffffffu, a1, 31);
        float e0 = expf(a0), e1 = expf(a1);
        sm.egc[lane] = e0;                sm.egc[lane + 32] = e1;
        sm.iegc[lane] = expf(-a0);        sm.iegc[lane + 32] = expf(-a1);
        sm.kdec[lane] = expf(glast - a0); sm.kdec[lane + 32] = expf(glast - a1);
        float b0 = sm.bst[lane], b1 = sm.bst[lane + 32];
        sm.kw[lane] = b0 * e0;            sm.kw[lane + 32] = b1 * e1;
        sm.negbe[lane] = -b0 * e0;        sm.negbe[lane + 32] = -b1 * e1;
    }
    __syncthreads();
    if (tid < CC) {
        size_t sb = (size_t)tile * 256;
        g_sc[sb + tid] = sm.kw[tid];
        g_sc[sb + 64 + tid] = sm.kdec[tid];
        g_sc[sb + 128 + tid] = sm.bst[tid];
        if (tid == 0) g_sc[sb + 192] = sm.egc[CC - 1];
    }
#pragma unroll
    for (int it = 0; it < 4; ++it)
#pragma unroll
        for (int pp = 0; pp < 2; ++pp) {
            int rr = warp + it * 16 + pp * 8;
            size_t rb = (((size_t)b * S_LEN + s0 + rr) * NH + h) * (size_t)DK + lane * 4;
            float4 qv = *(const float4*)(gq + rb);
            float4 kv = *(const float4*)(gk + rb);
            float sq = qv.x*qv.x + qv.y*qv.y + qv.z*qv.z + qv.w*qv.w;
            float sk = kv.x*kv.x + kv.y*kv.y + kv.z*kv.z + kv.w*kv.w;
#pragma unroll
            for (int o = 16; o > 0; o >>= 1) {
                sq += __shfl_xor_sync(0xffffffffu, sq, o);
                sk += __shfl_xor_sync(0xffffffffu, sk, o);
            }
            float rqs = rsqrtf(sq + 1e-6f) * QSCALE * sm.egc[rr];
            float rks = rsqrtf(sk + 1e-6f);
            int c4 = lane * 4;
            unsigned hh, ll;
            bsplit2(kv.x * rks, kv.y * rks, hh, ll);
            *(unsigned*)&sm.khi[rr*KHS + c4] = hh; *(unsigned*)&sm.klo[rr*KHS + c4] = ll;
            g_k[0][t4 + rr*64 + lane*2] = hh; g_k[1][t4 + rr*64 + lane*2] = ll;
            bsplit2(kv.z * rks, kv.w * rks, hh, ll);
            *(unsigned*)&sm.khi[rr*KHS + c4+2] = hh; *(unsigned*)&sm.klo[rr*KHS + c4+2] = ll;
            g_k[0][t4 + rr*64 + lane*2 + 1] = hh; g_k[1][t4 + rr*64 + lane*2 + 1] = ll;
            bsplit2(qv.x * rqs, qv.y * rqs, hh, ll);
            *(unsigned*)&sm.qhi[rr*KHS + c4] = hh; *(unsigned*)&sm.qlo[rr*KHS + c4] = ll;
            g_qg[0][t4 + rr*64 + lane*2] = hh; g_qg[1][t4 + rr*64 + lane*2] = ll;
            bsplit2(qv.z * rqs, qv.w * rqs, hh, ll);
            *(unsigned*)&sm.qhi[rr*KHS + c4+2] = hh; *(unsigned*)&sm.qlo[rr*KHS + c4+2] = ll;
            g_qg[0][t4 + rr*64 + lane*2 + 1] = hh; g_qg[1][t4 + rr*64 + lane*2 + 1] = ll;
        }
    __syncthreads();

    {
        const int m0 = (warp >> 1) * 16, n0 = (warp & 1) * 32;
        float accG[4][4] = {}, accQ[4][4] = {};
        if (m0 + 15 >= n0) {
            unsigned aKh = sm_addr(&sm.khi[(m0+lr)*KHS + lc8]);
            unsigned aKl = sm_addr(&sm.klo[(m0+lr)*KHS + lc8]);
            unsigned aQh = sm_addr(&sm.qhi[(m0+lr)*KHS + lc8]);
            unsigned aQl = sm_addr(&sm.qlo[(m0+lr)*KHS + lc8]);
            unsigned b0a = sm_addr(&sm.khi[(n0+lr)*KHS + lc8]);
            unsigned b0b = sm_addr(&sm.klo[(n0+lr)*KHS + lc8]);
            unsigned b1a = sm_addr(&sm.khi[(n0+16+lr)*KHS + lc8]);
            unsigned b1b = sm_addr(&sm.klo[(n0+16+lr)*KHS + lc8]);
            const bool d1 = (m0+15 >= n0+8), d2 = (m0+15 >= n0+16), d3 = (m0+15 >= n0+24);
            for (int k0 = 0; k0 < DK; k0 += 16) {
                unsigned kh[4], kl[4], qh[4], ql[4], p0h[4], p0l[4];
                ldsm4(kh, aKh + k0*2); ldsm4(kl, aKl + k0*2);
                ldsm4(qh, aQh + k0*2); ldsm4(ql, aQl + k0*2);
                ldsm4(p0h, b0a + k0*2); ldsm4(p0l, b0b + k0*2);
                mma_p3(accG[0], kh, kl, p0h[0], p0h[2], p0l[0], p0l[2]);
                mma_p3(accQ[0], qh, ql, p0h[0], p0h[2], p0l[0], p0l[2]);
                if (d1) {
                    mma_p3(accG[1], kh, kl, p0h[1], p0h[3], p0l[1], p0l[3]);
                    mma_p3(accQ[1], qh, ql, p0h[1], p0h[3], p0l[1], p0l[3]);
                }
                if (d2) {
                    unsigned p1h[4], p1l[4];
                    ldsm4(p1h, b1a + k0*2); ldsm4(p1l, b1b + k0*2);
                    mma_p3(accG[2], kh, kl, p1h[0], p1h[2], p1l[0], p1l[2]);
                    mma_p3(accQ[2], qh, ql, p1h[0], p1h[2], p1l[0], p1l[2]);
                    if (d3) {
                        mma_p3(accG[3], kh, kl, p1h[1], p1h[3], p1l[1], p1l[3]);
                        mma_p3(accQ[3], qh, ql, p1h[1], p1h[3], p1l[1], p1l[3]);
                    }
                }
            }
        }
#pragma unroll
        for (int nt = 0; nt < 4; ++nt) {
            int j0 = n0 + nt * 8 + 2 * tig;
            float ie0 = sm.iegc[j0], ie1 = sm.iegc[j0 + 1];
#pragma unroll
            for (int rh = 0; rh < 2; ++rh) {
                int i = m0 + gq_ + rh * 8;
                float nb = sm.negbe[i];
                float av0 = (i > j0)      ? nb * ie0 * accG[nt][rh*2]   : 0.f;
                float av1 = (i > j0 + 1)  ? nb * ie1 * accG[nt][rh*2+1] : 0.f;
                float at0 = (i >= j0)     ? accQ[nt][rh*2]   * ie0 : 0.f;
                float at1 = (i >= j0 + 1) ? accQ[nt][rh*2+1] * ie1 : 0.f;
                unsigned hh, ll;
                bsplit2(av0, av1, hh, ll);
                *(unsigned*)&sm.abh[i*AS2 + j0] = hh;
                *(unsigned*)&sm.abl[i*AS2 + j0] = ll;
                bsplit2(at0, at1, hh, ll);
                g_at[0][t2 + i * 32 + (j0 >> 1)] = hh;
                g_at[1][t2 + i * 32 + (j0 >> 1)] = ll;
            }
        }
    }
    __syncthreads();
    if (warp < 4 && lane < 16) {
        const int r0 = warp * 16;
        float x[16];
#pragma unroll
        for (int r = 0; r < 16; ++r) {
            float acc = (r == lane) ? 1.f : 0.f;
#pragma unroll
            for (int j = 0; j < 16; ++j)
                if (j < r) {
                    float a = __bfloat162float(sm.abh[(r0+r)*AS2 + r0+j]) +
                              __bfloat162float(sm.abl[(r0+r)*AS2 + r0+j]);
                    acc += a * x[j];
                }
            x[r] = acc;
        }
        __syncwarp(0x0000ffffu);
#pragma unroll
        for (int r = 0; r < 16; ++r) {
            __nv_bfloat16 hi, lo; bsplit(x[r], hi, lo);
            sm.abh[(r0+r)*AS2 + r0 + lane] = hi;
            sm.abl[(r0+r)*AS2 + r0 + lane] = lo;
        }
    }
    __syncthreads();
    for (int w = tid; w < 2048; w += NT) {
        int i = w >> 5, jp = w & 31;
        g_ab[0][t2 + w] = *(unsigned*)&sm.abh[i*AS2 + 2*jp];
        g_ab[1][t2 + w] = *(unsigned*)&sm.abl[i*AS2 + 2*jp];
    }
}

// ===================== kernel 2: scan (R9 + shortened critical path) =====================
struct __align__(16) SmemS {
    float v[CC * VS];
    float vraw[CC * 32];
    float scb[2][256];
    __nv_bfloat16 khi[2][CC * KHS], klo[2][CC * KHS];
    __nv_bfloat16 qhi[CC * KHS], qlo[CC * KHS];
    __nv_bfloat16 shi[32 * KHS], slo[32 * KHS];
    __nv_bfloat16 abh[CC * AS2], abl[CC * AS2];
    __nv_bfloat16 ath[CC * AS2], atl[CC * AS2];
    __nv_bfloat16 vth[32 * VTS], vtl[32 * VTS];
    __nv_bfloat16 rh[32 * VTS], rl[32 * VTS];
};

__global__ __launch_bounds__(NT, 1)
void gdn_scan(const float* __restrict__ gv, float* __restrict__ gout) {
    extern __shared__ char smraw[];
    SmemS& s = *reinterpret_cast<SmemS*>(smraw);
    const int bh = blockIdx.x / SPLIT, split = blockIdx.x % SPLIT;
    const int b = bh / NH, h = bh % NH;
    const int tid = threadIdx.x, warp = tid >> 5, lane = tid & 31;
    const int gq_ = lane >> 2, tig = lane & 3;
    const int lr = lane & 15, lc8 = (lane >> 4) << 3;
    const int lr2 = lane & 7, lc2 = ((lane >> 3) & 1) << 3;
    const int tile0 = bh * NCHUNK;

    const __nv_bfloat16 bz = __float2bfloat16(0.f);
    for (int i = tid; i < 32 * KHS; i += NT) { s.shi[i] = bz; s.slo[i] = bz; }

#define LD_KVS(nn, bf) do { \
    unsigned t4 = (unsigned)(tile0 + (nn)) * 4096u; \
    for (int i = tid; i < 1024; i += NT) { int r = i >> 4, j = i & 15; \
        cpa16(&s.khi[bf][r*KHS + j*8], &g_k[0][t4 + r*64 + j*4]); \
        cpa16(&s.klo[bf][r*KHS + j*8], &g_k[1][t4 + r*64 + j*4]); } \
    for (int i = tid; i < 512; i += NT) { int r = i >> 3, c = (i & 7) * 4; \
        cpa16(&s.vraw[r*32 + c], \
              gv + (((size_t)b * S_LEN + (nn) * CC + r) * NH + h) * (size_t)DV + \
              split * DVS + c); } \
    for (int i = tid; i < 64; i += NT) \
        cpa16(&s.scb[bf][i*4], &g_sc[(size_t)(tile0 + (nn)) * 256 + i*4]); \
    asm volatile("cp.async.commit_group;\n"); } while (0)
#define LD_AB(nn) do { \
    unsigned t2 = (unsigned)(tile0 + (nn)) * 2048u; \
    for (int i = tid; i < 512; i += NT) { int r = i >> 3, j = i & 7; \
        cpa16(&s.abh[r*AS2 + j*8], &g_ab[0][t2 + r*32 + j*4]); \
        cpa16(&s.abl[r*AS2 + j*8], &g_ab[1][t2 + r*32 + j*4]); } \
    asm volatile("cp.async.commit_group;\n"); } while (0)
#define LD_QA(nn) do { \
    unsigned t4 = (unsigned)(tile0 + (nn)) * 4096u; \
    unsigned t2 = (unsigned)(tile0 + (nn)) * 2048u; \
    for (int i = tid; i < 1024; i += NT) { int r = i >> 4, j = i & 15; \
        cpa16(&s.qhi[r*KHS + j*8], &g_qg[0][t4 + r*64 + j*4]); \
        cpa16(&s.qlo[r*KHS + j*8], &g_qg[1][t4 + r*64 + j*4]); } \
    for (int i = tid; i < 512; i += NT) { int r = i >> 3, j = i & 7; \
        cpa16(&s.ath[r*AS2 + j*8], &g_at[0][t2 + r*32 + j*4]); \
        cpa16(&s.atl[r*AS2 + j*8], &g_at[1][t2 + r*32 + j*4]); } \
    asm volatile("cp.async.commit_group;\n"); } while (0)

    LD_KVS(0, 0); LD_AB(0); LD_QA(0);

    for (int n = 0; n < NCHUNK; ++n) {
        const int cur = n & 1, s0 = n * CC;
        const int nn1 = (n + 1 < NCHUNK) ? n + 1 : n;
        asm volatile("cp.async.wait_group 2;\n");       // KVS(n)
        __syncthreads();
        const float* sc = s.scb[cur];

        // P2: rhs = vraw*beta - kw*(K@S); warps 0,1 (c<16) write rh/rl direct
        {
            const int m0 = (warp & 1) * 16, n0 = (warp >> 1) * 16;
            float acc[2][4] = {};
            unsigned aSh = sm_addr(&s.shi[(m0+lr)*KHS + lc8]);
            unsigned aSl = sm_addr(&s.slo[(m0+lr)*KHS + lc8]);
            unsigned bKh = sm_addr(&s.khi[cur][(n0+lr)*KHS + lc8]);
            unsigned bKl = sm_addr(&s.klo[cur][(n0+lr)*KHS + lc8]);
            for (int k0 = 0; k0 < DK; k0 += 16) {
                unsigned ah[4], al[4], bh4[4], bl4[4];
                ldsm4(ah, aSh + k0*2); ldsm4(al, aSl + k0*2);
                ldsm4(bh4, bKh + k0*2); ldsm4(bl4, bKl + k0*2);
                mma_p3(acc[0], ah, al, bh4[0], bh4[2], bl4[0], bl4[2]);
                mma_p3(acc[1], ah, al, bh4[1], bh4[3], bl4[1], bl4[3]);
            }
#pragma unroll
            for (int nt = 0; nt < 2; ++nt)
#pragma unroll
                for (int rh2 = 0; rh2 < 2; ++rh2) {
                    int i = m0 + gq_ + rh2 * 8;            // dv
                    int j0 = n0 + nt * 8 + 2 * tig;        // c (even)
                    float vb0 = s.vraw[j0*32 + i] * sc[128 + j0]
                                - sc[j0] * acc[nt][rh2*2];
                    float vb1 = s.vraw[(j0+1)*32 + i] * sc[128 + j0 + 1]
                                - sc[j0 + 1] * acc[nt][rh2*2 + 1];
                    if (n0 == 0) {     // block0 -> rh/rl bf16 pairs
                        unsigned hh, ll; bsplit2(vb0, vb1, hh, ll);
                        *(unsigned*)&s.rh[i*VTS + j0] = hh;
                        *(unsigned*)&s.rl[i*VTS + j0] = ll;
                    } else {
                        s.v[j0 * VS + i] = vb0;
                        s.v[(j0 + 1) * VS + i] = vb1;
                    }
                }
        }
        __syncthreads();                                 // vraw free; rh visible
        LD_KVS(nn1, cur ^ 1);
        asm volatile("cp.async.wait_group 2;\n");        // AB(n)
        __syncthreads();

        // solve blocks via MMA (validated)
#pragma unroll
        for (int blk = 0; blk < 4; ++blk) {
            if (blk > 0) {
                if (warp < 4) {
                    const int i0 = blk * 16, n0 = warp * 8;
                    float acc[4] = {0, 0, 0, 0};
                    unsigned aAh = sm_addr(&s.abh[(i0+lr)*AS2 + lc8]);
                    unsigned aAl = sm_addr(&s.abl[(i0+lr)*AS2 + lc8]);
                    unsigned bVh = sm_addr(&s.vth[(n0+lr2)*VTS + lc2]);
                    unsigned bVl = sm_addr(&s.vtl[(n0+lr2)*VTS + lc2]);
                    for (int ks = 0; ks < blk; ++ks) {
                        unsigned ah[4], al[4], bh2[2], bl2[2];
                        ldsm4(ah, aAh + ks*32); ldsm4(al, aAl + ks*32);
                        ldsm2(bh2, bVh + ks*32); ldsm2(bl2, bVl + ks*32);
                        mma_p3(acc, ah, al, bh2[0], bh2[1], bl2[0], bl2[1]);
                    }
#pragma unroll
                    for (int e = 0; e < 4; ++e) {
                        int i = i0 + gq_ + ((e >> 1) << 3);
                        int dv = n0 + 2 * tig + (e & 1);
                        float r = s.v[i * VS + dv] + acc[e];
                        __nv_bfloat16 hi, lo; bsplit(r, hi, lo);
                        s.rh[dv * VTS + (i - i0)] = hi;
                        s.rl[dv * VTS + (i - i0)] = lo;
                    }
                }
                __syncthreads();
            }
            if (warp < 4) {
                const int i0 = blk * 16, n0 = warp * 8;
                unsigned ah[4], al[4], bh2[2], bl2[2];
                ldsm4(ah, sm_addr(&s.abh[(i0+lr)*AS2 + i0 + lc8]));
                ldsm4(al, sm_addr(&s.abl[(i0+lr)*AS2 + i0 + lc8]));
                ldsm2(bh2, sm_addr(&s.rh[(n0+lr2)*VTS + lc2]));
                ldsm2(bl2, sm_addr(&s.rl[(n0+lr2)*VTS + lc2]));
                float acc[4] = {0, 0, 0, 0};
                mma_p3(acc, ah, al, bh2[0], bh2[1], bl2[0], bl2[1]);
#pragma unroll
                for (int e = 0; e < 4; ++e) {
                    int i = i0 + gq_ + ((e >> 1) << 3);
                    int dv = n0 + 2 * tig + (e & 1);
                    s.v[i * VS + dv] = acc[e];
                    __nv_bfloat16 hi, lo; bsplit(acc[e], hi, lo);
                    s.vth[dv * VTS + i] = hi;
                    s.vtl[dv * VTS + i] = lo;
                }
            }
            __syncthreads();
        }
        LD_AB(nn1);

        // vd = (v_new * kdec)^T -> rh/rl
        {
            int dv = tid >> 3, c0 = (tid & 7) * 8;
#pragma unroll
            for (int cc2 = 0; cc2 < 8; cc2 += 2) {
                int c = c0 + cc2;
                unsigned hh, ll;
                bsplit2(s.v[c * VS + dv] * sc[64 + c],
                        s.v[(c + 1) * VS + dv] * sc[64 + c + 1], hh, ll);
                *(unsigned*)&s.rh[dv*VTS + c] = hh;
                *(unsigned*)&s.rl[dv*VTS + c] = ll;
            }
        }
        asm volatile("cp.async.wait_group 2;\n");        // QA(n)
        __syncthreads();

        // P4 (out) + P5-MMA fused
        float acc5[4][4] = {};
        {
            const int m0 = (warp & 1) * 16, n0 = (warp >> 1) * 16;
            float acc[2][4] = {};
            {
                unsigned aSh = sm_addr(&s.shi[(m0+lr)*KHS + lc8]);
                unsigned aSl = sm_addr(&s.slo[(m0+lr)*KHS + lc8]);
                unsigned bQh = sm_addr(&s.qhi[(n0+lr)*KHS + lc8]);
                unsigned bQl = sm_addr(&s.qlo[(n0+lr)*KHS + lc8]);
                for (int k0 = 0; k0 < DK; k0 += 16) {
                    unsigned ah[4], al[4], bh4[4], bl4[4];
                    ldsm4(ah, aSh + k0*2); ldsm4(al, aSl + k0*2);
                    ldsm4(bh4, bQh + k0*2); ldsm4(bl4, bQl + k0*2);
                    mma_p3(acc[0], ah, al, bh4[0], bh4[2], bl4[0], bl4[2]);
                    mma_p3(acc[1], ah, al, bh4[1], bh4[3], bl4[1], bl4[3]);
                }
            }
            {
                unsigned aVh = sm_addr(&s.vth[(m0+lr)*VTS + lc8]);
                unsigned aVl = sm_addr(&s.vtl[(m0+lr)*VTS + lc8]);
                unsigned bAh = sm_addr(&s.ath[(n0+lr)*AS2 + lc8]);
                unsigned bAl = sm_addr(&s.atl[(n0+lr)*AS2 + lc8]);
                for (int k0 = 0; k0 < CC; k0 += 16) {
                    unsigned ah[4], al[4], bh4[4], bl4[4];
                    ldsm4(ah, aVh + k0*2); ldsm4(al, aVl + k0*2);
                    ldsm4(bh4, bAh + k0*2); ldsm4(bl4, bAl + k0*2);
                    mma_p3(acc[0], ah, al, bh4[0], bh4[2], bl4[0], bl4[2]);
                    mma_p3(acc[1], ah, al, bh4[1], bh4[3], bl4[1], bl4[3]);
                }
            }
#pragma unroll
            for (int nt = 0; nt < 2; ++nt)
#pragma unroll
                for (int e = 0; e < 4; ++e) {
                    int dv = m0 + gq_ + ((e >> 1) << 3);
                    int c = n0 + nt * 8 + 2 * tig + (e & 1);
                    gout[(((size_t)b * S_LEN + s0 + c) * NH + h) * (size_t)DV +
                         split * DVS + dv] = acc[nt][e];
                }
        }
        {
            const int m0 = (warp & 1) * 16, n0 = (warp >> 1) * 32;
            unsigned aVh = sm_addr(&s.rh[(m0+lr)*VTS + lc8]);
            unsigned aVl = sm_addr(&s.rl[(m0+lr)*VTS + lc8]);
            const __nv_bfloat16* kb_h = s.khi[cur];
            const __nv_bfloat16* kb_l = s.klo[cur];
            for (int k0 = 0; k0 < CC; k0 += 16) {
                unsigned ah[4], al[4];
                ldsm4(ah, aVh + k0*2); ldsm4(al, aVl + k0*2);
#pragma unroll
                for (int nt = 0; nt < 4; ++nt) {
                    int nn = n0 + nt * 8 + gq_;
                    unsigned bhh[2], bll[2];
                    ldBtrans(kb_h, KHS, nn, k0, tig, bhh);
                    ldBtrans(kb_l, KHS, nn, k0, tig, bll);
                    mma_p3(acc5[nt], ah, al, bhh[0], bhh[1], bll[0], bll[1]);
                }
            }
        }
        __syncthreads();          // P4 qg/attn reads + P5 reads done
        LD_QA(nn1);
        // state RMW
        {
            const int m0 = (warp & 1) * 16, n0 = (warp >> 1) * 32;
            float egl = sc[192];
#pragma unroll
            for (int nt = 0; nt < 4; ++nt)
#pragma unroll
                for (int e = 0; e < 4; ++e) {
                    int dv = m0 + gq_ + ((e >> 1) << 3);
                    int dk = n0 + nt * 8 + 2 * tig + (e & 1);
                    float s_old = __bfloat162float(s.shi[dv * KHS + dk]) +
                                  __bfloat162float(s.slo[dv * KHS + dk]);
                    float sv = s_old * egl + acc5[nt][e];
                    __nv_bfloat16 hi, lo; bsplit(sv, hi, lo);
                    s.shi[dv * KHS + dk] = hi;
                    s.slo[dv * KHS + dk] = lo;
                }
        }
    }
}

extern "C" void kernel_launch(void* const* d_in, const int* in_sizes, int n_in,
                              void* d_out, int out_size) {
    const float* q = (const float*)d_in[0];
    const float* k = (const float*)d_in[1];
    const float* v = (const float*)d_in[2];
    const float* g = (const float*)d_in[3];
    const float* beta = (const float*)d_in[4];
    float* out = (float*)d_out;
    int B = in_sizes[0] / (S_LEN * NH * DK);
    if (B < 1) B = 1;
    cudaFuncSetAttribute(gdn_prep, cudaFuncAttributeMaxDynamicSharedMemorySize,
                         (int)sizeof(SmemP));
    cudaFuncSetAttribute(gdn_scan, cudaFuncAttributeMaxDynamicSharedMemorySize,
                         (int)sizeof(SmemS));
    gdn_prep<<<B * NH * NCHUNK, NT, sizeof(SmemP)>>>(q, k, g, beta);
    gdn_scan<<<B * NH * SPLIT, NT, sizeof(SmemS)>>>(v, out);
}

// round 13
// speedup vs baseline: 1.6648x; 1.0087x over previous
#include <cuda_runtime.h>
#include <cuda_bf16.h>
#include <math.h>

#define S_LEN 4096
#define NH 16
#define DK 128
#define DV 128
#define CC 64
#define NCHUNK 64
#define NT 256
#define SPLIT 4
#define DVS 32
#define NTILES 2048
#define KHS 136
#define AS2 72
#define VS 36
#define VTS 72
#define KTS 72

// packed bf16 pair scratch ([0]=hi,[1]=lo)
__device__ unsigned g_k[2][NTILES * 4096];    // [c][dk pair]
__device__ unsigned g_qg[2][NTILES * 4096];   // [c][dk pair]
__device__ unsigned g_kdT[2][NTILES * 4096];  // [dk][c pair]  (k*kdec transposed)
__device__ unsigned g_ab[2][NTILES * 2048];   // [i][j pair]  (A strict-lower, Ti diag)
__device__ unsigned g_at[2][NTILES * 2048];   // [i][j pair]  (attn masked)
__device__ float g_sc[NTILES * 256];          // kw[64], kdec[64], beta[64], egl

__device__ __forceinline__ void bsplit(float x, __nv_bfloat16& hi, __nv_bfloat16& lo) {
    hi = __float2bfloat16(x);
    lo = __float2bfloat16(x - __bfloat162float(hi));
}
__device__ __forceinline__ void bsplit2(float x0, float x1, unsigned& h, unsigned& l) {
    __nv_bfloat16 h0 = __float2bfloat16(x0), h1 = __float2bfloat16(x1);
    __nv_bfloat16 g0 = __float2bfloat16(x0 - __bfloat162float(h0));
    __nv_bfloat16 g1 = __float2bfloat16(x1 - __bfloat162float(h1));
    h = (unsigned)*(unsigned short*)&h0 | ((unsigned)*(unsigned short*)&h1 << 16);
    l = (unsigned)*(unsigned short*)&g0 | ((unsigned)*(unsigned short*)&g1 << 16);
}
__device__ __forceinline__ unsigned sm_addr(const void* p) {
    return (unsigned)__cvta_generic_to_shared(p);
}
__device__ __forceinline__ void ldsm4(unsigned* r, unsigned a) {
    asm volatile("ldmatrix.sync.aligned.m8n8.x4.shared.b16 {%0,%1,%2,%3}, [%4];"
                 : "=r"(r[0]), "=r"(r[1]), "=r"(r[2]), "=r"(r[3]) : "r"(a));
}
__device__ __forceinline__ void ldsm2(unsigned* r, unsigned a) {
    asm volatile("ldmatrix.sync.aligned.m8n8.x2.shared.b16 {%0,%1}, [%2];"
                 : "=r"(r[0]), "=r"(r[1]) : "r"(a));
}
__device__ __forceinline__ void mma16816(float* d, unsigned a0, unsigned a1,
                                         unsigned a2, unsigned a3,
                                         unsigned b0, unsigned b1) {
    asm volatile("mma.sync.aligned.m16n8k16.row.col.f32.bf16.bf16.f32 "
                 "{%0,%1,%2,%3}, {%4,%5,%6,%7}, {%8,%9}, {%0,%1,%2,%3};\n"
                 : "+f"(d[0]), "+f"(d[1]), "+f"(d[2]), "+f"(d[3])
                 : "r"(a0), "r"(a1), "r"(a2), "r"(a3), "r"(b0), "r"(b1));
}
__device__ __forceinline__ void mma_p3(float* d, const unsigned* ah, const unsigned* al,
                                       unsigned bh0, unsigned bh1,
                                       unsigned bl0, unsigned bl1) {
    mma16816(d, ah[0], ah[1], ah[2], ah[3], bh0, bh1);
    mma16816(d, ah[0], ah[1], ah[2], ah[3], bl0, bl1);
    mma16816(d, al[0], al[1], al[2], al[3], bh0, bh1);
}
__device__ __forceinline__ void cpa16(void* dst, const void* src) {
    unsigned d = (unsigned)__cvta_generic_to_shared(dst);
    asm volatile("cp.async.cg.shared.global [%0], [%1], 16;\n" :: "r"(d), "l"(src));
}

// ===================== kernel 1: prep (R9 validated + kdT store) =====================
struct __align__(16) SmemP {
    float gst[CC], bst[CC], egc[CC], iegc[CC], kdec[CC], kw[CC], negbe[CC];
    __nv_bfloat16 khi[CC * KHS], klo[CC * KHS], qhi[CC * KHS], qlo[CC * KHS];
    __nv_bfloat16 abh[CC * AS2], abl[CC * AS2];
};

__global__ __launch_bounds__(NT, 2)
void gdn_prep(const float* __restrict__ gq, const float* __restrict__ gk,
              const float* __restrict__ gg, const float* __restrict__ gb) {
    extern __shared__ char smraw[];
    SmemP& sm = *reinterpret_cast<SmemP*>(smraw);
    const int tile = blockIdx.x, bh = tile / NCHUNK, n = tile % NCHUNK;
    const int b = bh / NH, h = bh % NH, s0 = n * CC;
    const int tid = threadIdx.x, warp = tid >> 5, lane = tid & 31;
    const int gq_ = lane >> 2, tig = lane & 3;
    const int lr = lane & 15, lc8 = (lane >> 4) << 3;
    const unsigned t4 = (unsigned)tile * 4096u, t2 = (unsigned)tile * 2048u;
    const float QSCALE = 0.08838834764831845f;

    if (tid < CC) {
        size_t gi = ((size_t)b * S_LEN + s0 + tid) * NH + h;
        sm.gst[tid] = gg[gi];
        sm.bst[tid] = gb[gi];
    }
    __syncthreads();
    if (warp == 0) {
        float a0 = sm.gst[lane], a1 = sm.gst[lane + 32];
#pragma unroll
        for (int o = 1; o < 32; o <<= 1) {
            float t = __shfl_up_sync(0xffffffffu, a0, o);
            if (lane >= o) a0 += t;
        }
        float tot0 = __shfl_sync(0xffffffffu, a0, 31);
#pragma unroll
        for (int o = 1; o < 32; o <<= 1) {
            float t = __shfl_up_sync(0xffffffffu, a1, o);
            if (lane >= o) a1 += t;
        }
        a1 += tot0;
        float glast = __shfl_sync(0xffffffffu, a1, 31);
        float e0 = expf(a0), e1 = expf(a1);
        sm.egc[lane] = e0;                sm.egc[lane + 32] = e1;
        sm.iegc[lane] = expf(-a0);        sm.iegc[lane + 32] = expf(-a1);
        sm.kdec[lane] = expf(glast - a0); sm.kdec[lane + 32] = expf(glast - a1);
        float b0 = sm.bst[lane], b1 = sm.bst[lane + 32];
        sm.kw[lane] = b0 * e0;            sm.kw[lane + 32] = b1 * e1;
        sm.negbe[lane] = -b0 * e0;        sm.negbe[lane + 32] = -b1 * e1;
    }
    __syncthreads();
    if (tid < CC) {
        size_t sb = (size_t)tile * 256;
        g_sc[sb + tid] = sm.kw[tid];
        g_sc[sb + 64 + tid] = sm.kdec[tid];
        g_sc[sb + 128 + tid] = sm.bst[tid];
        if (tid == 0) g_sc[sb + 192] = sm.egc[CC - 1];
    }
#pragma unroll
    for (int it = 0; it < 4; ++it)
#pragma unroll
        for (int pp = 0; pp < 2; ++pp) {
            int rr = warp + it * 16 + pp * 8;
            size_t rb = (((size_t)b * S_LEN + s0 + rr) * NH + h) * (size_t)DK + lane * 4;
            float4 qv = *(const float4*)(gq + rb);
            float4 kv = *(const float4*)(gk + rb);
            float sq = qv.x*qv.x + qv.y*qv.y + qv.z*qv.z + qv.w*qv.w;
            float sk = kv.x*kv.x + kv.y*kv.y + kv.z*kv.z + kv.w*kv.w;
#pragma unroll
            for (int o = 16; o > 0; o >>= 1) {
                sq += __shfl_xor_sync(0xffffffffu, sq, o);
                sk += __shfl_xor_sync(0xffffffffu, sk, o);
            }
            float rqs = rsqrtf(sq + 1e-6f) * QSCALE * sm.egc[rr];
            float rks = rsqrtf(sk + 1e-6f);
            int c4 = lane * 4;
            unsigned hh, ll;
            bsplit2(kv.x * rks, kv.y * rks, hh, ll);
            *(unsigned*)&sm.khi[rr*KHS + c4] = hh; *(unsigned*)&sm.klo[rr*KHS + c4] = ll;
            g_k[0][t4 + rr*64 + lane*2] = hh; g_k[1][t4 + rr*64 + lane*2] = ll;
            bsplit2(kv.z * rks, kv.w * rks, hh, ll);
            *(unsigned*)&sm.khi[rr*KHS + c4+2] = hh; *(unsigned*)&sm.klo[rr*KHS + c4+2] = ll;
            g_k[0][t4 + rr*64 + lane*2 + 1] = hh; g_k[1][t4 + rr*64 + lane*2 + 1] = ll;
            bsplit2(qv.x * rqs, qv.y * rqs, hh, ll);
            *(unsigned*)&sm.qhi[rr*KHS + c4] = hh; *(unsigned*)&sm.qlo[rr*KHS + c4] = ll;
            g_qg[0][t4 + rr*64 + lane*2] = hh; g_qg[1][t4 + rr*64 + lane*2] = ll;
            bsplit2(qv.z * rqs, qv.w * rqs, hh, ll);
            *(unsigned*)&sm.qhi[rr*KHS + c4+2] = hh; *(unsigned*)&sm.qlo[rr*KHS + c4+2] = ll;
            g_qg[0][t4 + rr*64 + lane*2 + 1] = hh; g_qg[1][t4 + rr*64 + lane*2 + 1] = ll;
        }
    __syncthreads();

    {
        const int m0 = (warp >> 1) * 16, n0 = (warp & 1) * 32;
        float accG[4][4] = {}, accQ[4][4] = {};
        if (m0 + 15 >= n0) {
            unsigned aKh = sm_addr(&sm.khi[(m0+lr)*KHS + lc8]);
            unsigned aKl = sm_addr(&sm.klo[(m0+lr)*KHS + lc8]);
            unsigned aQh = sm_addr(&sm.qhi[(m0+lr)*KHS + lc8]);
            unsigned aQl = sm_addr(&sm.qlo[(m0+lr)*KHS + lc8]);
            unsigned b0a = sm_addr(&sm.khi[(n0+lr)*KHS + lc8]);
            unsigned b0b = sm_addr(&sm.klo[(n0+lr)*KHS + lc8]);
            unsigned b1a = sm_addr(&sm.khi[(n0+16+lr)*KHS + lc8]);
            unsigned b1b = sm_addr(&sm.klo[(n0+16+lr)*KHS + lc8]);
            const bool d1 = (m0+15 >= n0+8), d2 = (m0+15 >= n0+16), d3 = (m0+15 >= n0+24);
            for (int k0 = 0; k0 < DK; k0 += 16) {
                unsigned kh[4], kl[4], qh[4], ql[4], p0h[4], p0l[4];
                ldsm4(kh, aKh + k0*2); ldsm4(kl, aKl + k0*2);
                ldsm4(qh, aQh + k0*2); ldsm4(ql, aQl + k0*2);
                ldsm4(p0h, b0a + k0*2); ldsm4(p0l, b0b + k0*2);
                mma_p3(accG[0], kh, kl, p0h[0], p0h[2], p0l[0], p0l[2]);
                mma_p3(accQ[0], qh, ql, p0h[0], p0h[2], p0l[0], p0l[2]);
                if (d1) {
                    mma_p3(accG[1], kh, kl, p0h[1], p0h[3], p0l[1], p0l[3]);
                    mma_p3(accQ[1], qh, ql, p0h[1], p0h[3], p0l[1], p0l[3]);
                }
                if (d2) {
                    unsigned p1h[4], p1l[4];
                    ldsm4(p1h, b1a + k0*2); ldsm4(p1l, b1b + k0*2);
                    mma_p3(accG[2], kh, kl, p1h[0], p1h[2], p1l[0], p1l[2]);
                    mma_p3(accQ[2], qh, ql, p1h[0], p1h[2], p1l[0], p1l[2]);
                    if (d3) {
                        mma_p3(accG[3], kh, kl, p1h[1], p1h[3], p1l[1], p1l[3]);
                        mma_p3(accQ[3], qh, ql, p1h[1], p1h[3], p1l[1], p1l[3]);
                    }
                }
            }
        }
#pragma unroll
        for (int nt = 0; nt < 4; ++nt) {
            int j0 = n0 + nt * 8 + 2 * tig;
            float ie0 = sm.iegc[j0], ie1 = sm.iegc[j0 + 1];
#pragma unroll
            for (int rh = 0; rh < 2; ++rh) {
                int i = m0 + gq_ + rh * 8;
                float nb = sm.negbe[i];
                float av0 = (i > j0)      ? nb * ie0 * accG[nt][rh*2]   : 0.f;
                float av1 = (i > j0 + 1)  ? nb * ie1 * accG[nt][rh*2+1] : 0.f;
                float at0 = (i >= j0)     ? accQ[nt][rh*2]   * ie0 : 0.f;
                float at1 = (i >= j0 + 1) ? accQ[nt][rh*2+1] * ie1 : 0.f;
                unsigned hh, ll;
                bsplit2(av0, av1, hh, ll);
                *(unsigned*)&sm.abh[i*AS2 + j0] = hh;
                *(unsigned*)&sm.abl[i*AS2 + j0] = ll;
                bsplit2(at0, at1, hh, ll);
                g_at[0][t2 + i * 32 + (j0 >> 1)] = hh;
                g_at[1][t2 + i * 32 + (j0 >> 1)] = ll;
            }
        }
    }
    __syncthreads();
    // invert diag blocks (warps 0-3); kdT store (warps 4-7, from R11 validated)
    if (warp < 4) {
        const int r0 = warp * 16;
        if (lane < 16) {
            float x[16];
#pragma unroll
            for (int r = 0; r < 16; ++r) {
                float acc = (r == lane) ? 1.f : 0.f;
#pragma unroll
                for (int j = 0; j < 16; ++j)
                    if (j < r) {
                        float a = __bfloat162float(sm.abh[(r0+r)*AS2 + r0+j]) +
                                  __bfloat162float(sm.abl[(r0+r)*AS2 + r0+j]);
                        acc += a * x[j];
                    }
                x[r] = acc;
            }
            __syncwarp(0x0000ffffu);
#pragma unroll
            for (int r = 0; r < 16; ++r) {
                __nv_bfloat16 hi, lo; bsplit(x[r], hi, lo);
                sm.abh[(r0+r)*AS2 + r0 + lane] = hi;
                sm.abl[(r0+r)*AS2 + r0 + lane] = lo;
            }
        }
    } else {
        int t = (warp - 4) * 32 + lane;
        for (int w = t; w < 4096; w += 128) {
            int dk = w >> 5, c0 = (w & 31) * 2;
            float v0 = (__bfloat162float(sm.khi[c0*KHS + dk]) +
                        __bfloat162float(sm.klo[c0*KHS + dk])) * sm.kdec[c0];
            float v1 = (__bfloat162float(sm.khi[(c0+1)*KHS + dk]) +
                        __bfloat162float(sm.klo[(c0+1)*KHS + dk])) * sm.kdec[c0 + 1];
            unsigned hh, ll; bsplit2(v0, v1, hh, ll);
            g_kdT[0][t4 + w] = hh;
            g_kdT[1][t4 + w] = ll;
        }
    }
    __syncthreads();
    for (int w = tid; w < 2048; w += NT) {
        int i = w >> 5, jp = w & 31;
        g_ab[0][t2 + w] = *(unsigned*)&sm.abh[i*AS2 + 2*jp];
        g_ab[1][t2 + w] = *(unsigned*)&sm.abl[i*AS2 + 2*jp];
    }
}

// ===================== kernel 2: scan =====================
struct __align__(16) SmemS {
    float v[CC * VS];
    float vraw[CC * 32];
    float scb[2][256];
    __nv_bfloat16 khi[CC * KHS], klo[CC * KHS];      // single-buffered (P2 only)
    __nv_bfloat16 qhi[CC * KHS], qlo[CC * KHS];
    __nv_bfloat16 shi[32 * KHS], slo[32 * KHS];
    __nv_bfloat16 abh[CC * AS2], abl[CC * AS2];
    __nv_bfloat16 ath[CC * AS2], atl[CC * AS2];
    __nv_bfloat16 kth[DK * KTS], ktl[DK * KTS];      // kdT
    __nv_bfloat16 vth[32 * VTS], vtl[32 * VTS];
    __nv_bfloat16 rh[32 * VTS], rl[32 * VTS];
};

__global__ __launch_bounds__(NT, 1)
void gdn_scan(const float* __restrict__ gv, float* __restrict__ gout) {
    extern __shared__ char smraw[];
    SmemS& s = *reinterpret_cast<SmemS*>(smraw);
    const int bh = blockIdx.x / SPLIT, split = blockIdx.x % SPLIT;
    const int b = bh / NH, h = bh % NH;
    const int tid = threadIdx.x, warp = tid >> 5, lane = tid & 31;
    const int gq_ = lane >> 2, tig = lane & 3;
    const int lr = lane & 15, lc8 = (lane >> 4) << 3;
    const int lr2 = lane & 7, lc2 = ((lane >> 3) & 1) << 3;
    const int tile0 = bh * NCHUNK;

    const __nv_bfloat16 bz = __float2bfloat16(0.f);
    for (int i = tid; i < 32 * KHS; i += NT) { s.shi[i] = bz; s.slo[i] = bz; }

#define LD_KVS(nn, bf) do { \
    unsigned t4 = (unsigned)(tile0 + (nn)) * 4096u; \
    for (int i = tid; i < 1024; i += NT) { int r = i >> 4, j = i & 15; \
        cpa16(&s.khi[r*KHS + j*8], &g_k[0][t4 + r*64 + j*4]); \
        cpa16(&s.klo[r*KHS + j*8], &g_k[1][t4 + r*64 + j*4]); } \
    for (int i = tid; i < 512; i += NT) { int r = i >> 3, c = (i & 7) * 4; \
        cpa16(&s.vraw[r*32 + c], \
              gv + (((size_t)b * S_LEN + (nn) * CC + r) * NH + h) * (size_t)DV + \
              split * DVS + c); } \
    for (int i = tid; i < 64; i += NT) \
        cpa16(&s.scb[bf][i*4], &g_sc[(size_t)(tile0 + (nn)) * 256 + i*4]); \
    asm volatile("cp.async.commit_group;\n"); } while (0)
#define LD_AB(nn) do { \
    unsigned t2 = (unsigned)(tile0 + (nn)) * 2048u; \
    for (int i = tid; i < 512; i += NT) { int r = i >> 3, j = i & 7; \
        cpa16(&s.abh[r*AS2 + j*8], &g_ab[0][t2 + r*32 + j*4]); \
        cpa16(&s.abl[r*AS2 + j*8], &g_ab[1][t2 + r*32 + j*4]); } \
    asm volatile("cp.async.commit_group;\n"); } while (0)
#define LD_QA(nn) do { \
    unsigned t4 = (unsigned)(tile0 + (nn)) * 4096u; \
    unsigned t2 = (unsigned)(tile0 + (nn)) * 2048u; \
    for (int i = tid; i < 1024; i += NT) { int r = i >> 4, j = i & 15; \
        cpa16(&s.qhi[r*KHS + j*8], &g_qg[0][t4 + r*64 + j*4]); \
        cpa16(&s.qlo[r*KHS + j*8], &g_qg[1][t4 + r*64 + j*4]); } \
    for (int i = tid; i < 512; i += NT) { int r = i >> 3, j = i & 7; \
        cpa16(&s.ath[r*AS2 + j*8], &g_at[0][t2 + r*32 + j*4]); \
        cpa16(&s.atl[r*AS2 + j*8], &g_at[1][t2 + r*32 + j*4]); } \
    for (int i = tid; i < 1024; i += NT) { int r = i >> 3, j = i & 7; \
        cpa16(&s.kth[r*KTS + j*8], &g_kdT[0][t4 + r*32 + j*4]); \
        cpa16(&s.ktl[r*KTS + j*8], &g_kdT[1][t4 + r*32 + j*4]); } \
    asm volatile("cp.async.commit_group;\n"); } while (0)

    LD_KVS(0, 0); LD_AB(0); LD_QA(0);

    for (int n = 0; n < NCHUNK; ++n) {
        const int cur = n & 1, s0 = n * CC;
        const int nn1 = (n + 1 < NCHUNK) ? n + 1 : n;
        asm volatile("cp.async.wait_group 2;\n");       // KVS(n)
        __syncthreads();
        const float* sc = s.scb[cur];

        // P2: rhs = vraw*beta - kw*(K@S); warps 0,1 (c<16) write rh/rl direct
        {
            const int m0 = (warp & 1) * 16, n0 = (warp >> 1) * 16;
            float acc[2][4] = {};
            unsigned aSh = sm_addr(&s.shi[(m0+lr)*KHS + lc8]);
            unsigned aSl = sm_addr(&s.slo[(m0+lr)*KHS + lc8]);
            unsigned bKh = sm_addr(&s.khi[(n0+lr)*KHS + lc8]);
            unsigned bKl = sm_addr(&s.klo[(n0+lr)*KHS + lc8]);
            for (int k0 = 0; k0 < DK; k0 += 16) {
                unsigned ah[4], al[4], bh4[4], bl4[4];
                ldsm4(ah, aSh + k0*2); ldsm4(al, aSl + k0*2);
                ldsm4(bh4, bKh + k0*2); ldsm4(bl4, bKl + k0*2);
                mma_p3(acc[0], ah, al, bh4[0], bh4[2], bl4[0], bl4[2]);
                mma_p3(acc[1], ah, al, bh4[1], bh4[3], bl4[1], bl4[3]);
            }
#pragma unroll
            for (int nt = 0; nt < 2; ++nt)
#pragma unroll
                for (int rh2 = 0; rh2 < 2; ++rh2) {
                    int i = m0 + gq_ + rh2 * 8;            // dv
                    int j0 = n0 + nt * 8 + 2 * tig;        // c (even)
                    float vb0 = s.vraw[j0*32 + i] * sc[128 + j0]
                                - sc[j0] * acc[nt][rh2*2];
                    float vb1 = s.vraw[(j0+1)*32 + i] * sc[128 + j0 + 1]
                                - sc[j0 + 1] * acc[nt][rh2*2 + 1];
                    if (n0 == 0) {
                        unsigned hh, ll; bsplit2(vb0, vb1, hh, ll);
                        *(unsigned*)&s.rh[i*VTS + j0] = hh;
                        *(unsigned*)&s.rl[i*VTS + j0] = ll;
                    } else {
                        s.v[j0 * VS + i] = vb0;
                        s.v[(j0 + 1) * VS + i] = vb1;
                    }
                }
        }
        __syncthreads();          // K/vraw free after this; rh visible
        LD_KVS(nn1, cur ^ 1);
        asm volatile("cp.async.wait_group 2;\n");        // AB(n)
        __syncthreads();

        // solve blocks via MMA (validated)
#pragma unroll
        for (int blk = 0; blk < 4; ++blk) {
            if (blk > 0) {
                if (warp < 4) {
                    const int i0 = blk * 16, n0 = warp * 8;
                    float acc[4] = {0, 0, 0, 0};
                    unsigned aAh = sm_addr(&s.abh[(i0+lr)*AS2 + lc8]);
                    unsigned aAl = sm_addr(&s.abl[(i0+lr)*AS2 + lc8]);
                    unsigned bVh = sm_addr(&s.vth[(n0+lr2)*VTS + lc2]);
                    unsigned bVl = sm_addr(&s.vtl[(n0+lr2)*VTS + lc2]);
                    for (int ks = 0; ks < blk; ++ks) {
                        unsigned ah[4], al[4], bh2[2], bl2[2];
                        ldsm4(ah, aAh + ks*32); ldsm4(al, aAl + ks*32);
                        ldsm2(bh2, bVh + ks*32); ldsm2(bl2, bVl + ks*32);
                        mma_p3(acc, ah, al, bh2[0], bh2[1], bl2[0], bl2[1]);
                    }
#pragma unroll
                    for (int e = 0; e < 4; ++e) {
                        int i = i0 + gq_ + ((e >> 1) << 3);
                        int dv = n0 + 2 * tig + (e & 1);
                        float r = s.v[i * VS + dv] + acc[e];
                        __nv_bfloat16 hi, lo; bsplit(r, hi, lo);
                        s.rh[dv * VTS + (i - i0)] = hi;
                        s.rl[dv * VTS + (i - i0)] = lo;
                    }
                }
                __syncthreads();
            }
            if (warp < 4) {
                const int i0 = blk * 16, n0 = warp * 8;
                unsigned ah[4], al[4], bh2[2], bl2[2];
                ldsm4(ah, sm_addr(&s.abh[(i0+lr)*AS2 + i0 + lc8]));
                ldsm4(al, sm_addr(&s.abl[(i0+lr)*AS2 + i0 + lc8]));
                ldsm2(bh2, sm_addr(&s.rh[(n0+lr2)*VTS + lc2]));
                ldsm2(bl2, sm_addr(&s.rl[(n0+lr2)*VTS + lc2]));
                float acc[4] = {0, 0, 0, 0};
                mma_p3(acc, ah, al, bh2[0], bh2[1], bl2[0], bl2[1]);
#pragma unroll
                for (int e = 0; e < 4; ++e) {
                    int i = i0 + gq_ + ((e >> 1) << 3);
                    int dv = n0 + 2 * tig + (e & 1);
                    s.v[i * VS + dv] = acc[e];
                    __nv_bfloat16 hi, lo; bsplit(acc[e], hi, lo);
                    s.vth[dv * VTS + i] = hi;
                    s.vtl[dv * VTS + i] = lo;
                }
            }
            __syncthreads();
        }
        LD_AB(nn1);
        asm volatile("cp.async.wait_group 2;\n");        // QA(n)
        __syncthreads();

        // P4 (out) + P5-MMA fused; P5: S += vn^T @ kdT (ldsm B, no scalar gather)
        float acc5[4][4] = {};
        {
            const int m0 = (warp & 1) * 16, n0 = (warp >> 1) * 16;
            float acc[2][4] = {};
            {
                unsigned aSh = sm_addr(&s.shi[(m0+lr)*KHS + lc8]);
                unsigned aSl = sm_addr(&s.slo[(m0+lr)*KHS + lc8]);
                unsigned bQh = sm_addr(&s.qhi[(n0+lr)*KHS + lc8]);
                unsigned bQl = sm_addr(&s.qlo[(n0+lr)*KHS + lc8]);
                for (int k0 = 0; k0 < DK; k0 += 16) {
                    unsigned ah[4], al[4], bh4[4], bl4[4];
                    ldsm4(ah, aSh + k0*2); ldsm4(al, aSl + k0*2);
                    ldsm4(bh4, bQh + k0*2); ldsm4(bl4, bQl + k0*2);
                    mma_p3(acc[0], ah, al, bh4[0], bh4[2], bl4[0], bl4[2]);
                    mma_p3(acc[1], ah, al, bh4[1], bh4[3], bl4[1], bl4[3]);
                }
            }
            {
                unsigned aVh = sm_addr(&s.vth[(m0+lr)*VTS + lc8]);
                unsigned aVl = sm_addr(&s.vtl[(m0+lr)*VTS + lc8]);
                unsigned bAh = sm_addr(&s.ath[(n0+lr)*AS2 + lc8]);
                unsigned bAl = sm_addr(&s.atl[(n0+lr)*AS2 + lc8]);
                for (int k0 = 0; k0 < CC; k0 += 16) {
                    unsigned ah[4], al[4], bh4[4], bl4[4];
                    ldsm4(ah, aVh + k0*2); ldsm4(al, aVl + k0*2);
                    ldsm4(bh4, bAh + k0*2); ldsm4(bl4, bAl + k0*2);
                    mma_p3(acc[0], ah, al, bh4[0], bh4[2], bl4[0], bl4[2]);
                    mma_p3(acc[1], ah, al, bh4[1], bh4[3], bl4[1], bl4[3]);
                }
            }
#pragma unroll
            for (int nt = 0; nt < 2; ++nt)
#pragma unroll
                for (int e = 0; e < 4; ++e) {
                    int dv = m0 + gq_ + ((e >> 1) << 3);
                    int c = n0 + nt * 8 + 2 * tig + (e & 1);
                    gout[(((size_t)b * S_LEN + s0 + c) * NH + h) * (size_t)DV +
                         split * DVS + dv] = acc[nt][e];
                }
        }
        {
            const int m0 = (warp & 1) * 16, n0 = (warp >> 1) * 32;
            unsigned aVh = sm_addr(&s.vth[(m0+lr)*VTS + lc8]);
            unsigned aVl = sm_addr(&s.vtl[(m0+lr)*VTS + lc8]);
            for (int k0 = 0; k0 < CC; k0 += 16) {
                unsigned ah[4], al[4];
                ldsm4(ah, aVh + k0*2); ldsm4(al, aVl + k0*2);
#pragma unroll
                for (int p = 0; p < 2; ++p) {
                    unsigned pbh[4], pbl[4];
                    ldsm4(pbh, sm_addr(&s.kth[(n0 + p*16 + lr)*KTS + lc8]) + k0*2);
                    ldsm4(pbl, sm_addr(&s.ktl[(n0 + p*16 + lr)*KTS + lc8]) + k0*2);
                    mma_p3(acc5[2*p],   ah, al, pbh[0], pbh[2], pbl[0], pbl[2]);
                    mma_p3(acc5[2*p+1], ah, al, pbh[1], pbh[3], pbl[1], pbl[3]);
                }
            }
        }
        __syncthreads();          // P4/P5 smem reads done
        LD_QA(nn1);
        // state RMW
        {
            const int m0 = (warp & 1) * 16, n0 = (warp >> 1) * 32;
            float egl = sc[192];
#pragma unroll
            for (int nt = 0; nt < 4; ++nt)
#pragma unroll
                for (int e = 0; e < 4; ++e) {
                    int dv = m0 + gq_ + ((e >> 1) << 3);
                    int dk = n0 + nt * 8 + 2 * tig + (e & 1);
                    float s_old = __bfloat162float(s.shi[dv * KHS + dk]) +
                                  __bfloat162float(s.slo[dv * KHS + dk]);
                    float sv = s_old * egl + acc5[nt][e];
                    __nv_bfloat16 hi, lo; bsplit(sv, hi, lo);
                    s.shi[dv * KHS + dk] = hi;
                    s.slo[dv * KHS + dk] = lo;
                }
        }
    }
}

extern "C" void kernel_launch(void* const* d_in, const int* in_sizes, int n_in,
                              void* d_out, int out_size) {
    const float* q = (const float*)d_in[0];
    const float* k = (const float*)d_in[1];
    const float* v = (const float*)d_in[2];
    const float* g = (const float*)d_in[3];
    const float* beta = (const float*)d_in[4];
    float* out = (float*)d_out;
    int B = in_sizes[0] / (S_LEN * NH * DK);
    if (B < 1) B = 1;
    cudaFuncSetAttribute(gdn_prep, cudaFuncAttributeMaxDynamicSharedMemorySize,
                         (int)sizeof(SmemP));
    cudaFuncSetAttribute(gdn_scan, cudaFuncAttributeMaxDynamicSharedMemorySize,
                         (int)sizeof(SmemS));
    gdn_prep<<<B * NH * NCHUNK, NT, sizeof(SmemP)>>>(q, k, g, beta);
    gdn_scan<<<B * NH * SPLIT, NT, sizeof(SmemS)>>>(v, out);
}

// round 14
// speedup vs baseline: 1.7121x; 1.0284x over previous
#include <cuda_runtime.h>
#include <cuda_bf16.h>
#include <math.h>

#define S_LEN 4096
#define NH 16
#define DK 128
#define DV 128
#define CC 64
#define NCHUNK 64
#define NT 256
#define SPLIT 4
#define DVS 32
#define NTILES 2048
#define KHS 136
#define AS2 72
#define VS 36
#define VTS 72
#define KTS 72

// packed bf16 pair scratch ([0]=hi,[1]=lo)
__device__ unsigned g_k[2][NTILES * 4096];    // [c][dk pair]
__device__ unsigned g_qg[2][NTILES * 4096];   // [c][dk pair]
__device__ unsigned g_kdT[2][NTILES * 4096];  // [dk][c pair]
__device__ unsigned g_ab[2][NTILES * 2048];   // [i][j pair]
__device__ unsigned g_at[2][NTILES * 2048];   // [i][j pair]
__device__ float g_sc[NTILES * 256];          // kw[64], kdec[64], beta[64], egl

__device__ __forceinline__ void bsplit(float x, __nv_bfloat16& hi, __nv_bfloat16& lo) {
    hi = __float2bfloat16(x);
    lo = __float2bfloat16(x - __bfloat162float(hi));
}
__device__ __forceinline__ void bsplit2(float x0, float x1, unsigned& h, unsigned& l) {
    __nv_bfloat16 h0 = __float2bfloat16(x0), h1 = __float2bfloat16(x1);
    __nv_bfloat16 g0 = __float2bfloat16(x0 - __bfloat162float(h0));
    __nv_bfloat16 g1 = __float2bfloat16(x1 - __bfloat162float(h1));
    h = (unsigned)*(unsigned short*)&h0 | ((unsigned)*(unsigned short*)&h1 << 16);
    l = (unsigned)*(unsigned short*)&g0 | ((unsigned)*(unsigned short*)&g1 << 16);
}
__device__ __forceinline__ float2 upk(unsigned h, unsigned l) {
    __nv_bfloat162 a = *reinterpret_cast<__nv_bfloat162*>(&h);
    __nv_bfloat162 b = *reinterpret_cast<__nv_bfloat162*>(&l);
    return make_float2(__bfloat162float(a.x) + __bfloat162float(b.x),
                       __bfloat162float(a.y) + __bfloat162float(b.y));
}
__device__ __forceinline__ unsigned sm_addr(const void* p) {
    return (unsigned)__cvta_generic_to_shared(p);
}
__device__ __forceinline__ void ldsm4(unsigned* r, unsigned a) {
    asm volatile("ldmatrix.sync.aligned.m8n8.x4.shared.b16 {%0,%1,%2,%3}, [%4];"
                 : "=r"(r[0]), "=r"(r[1]), "=r"(r[2]), "=r"(r[3]) : "r"(a));
}
__device__ __forceinline__ void ldsm2(unsigned* r, unsigned a) {
    asm volatile("ldmatrix.sync.aligned.m8n8.x2.shared.b16 {%0,%1}, [%2];"
                 : "=r"(r[0]), "=r"(r[1]) : "r"(a));
}
__device__ __forceinline__ void mma16816(float* d, unsigned a0, unsigned a1,
                                         unsigned a2, unsigned a3,
                                         unsigned b0, unsigned b1) {
    asm volatile("mma.sync.aligned.m16n8k16.row.col.f32.bf16.bf16.f32 "
                 "{%0,%1,%2,%3}, {%4,%5,%6,%7}, {%8,%9}, {%0,%1,%2,%3};\n"
                 : "+f"(d[0]), "+f"(d[1]), "+f"(d[2]), "+f"(d[3])
                 : "r"(a0), "r"(a1), "r"(a2), "r"(a3), "r"(b0), "r"(b1));
}
__device__ __forceinline__ void mma_p3(float* d, const unsigned* ah, const unsigned* al,
                                       unsigned bh0, unsigned bh1,
                                       unsigned bl0, unsigned bl1) {
    mma16816(d, ah[0], ah[1], ah[2], ah[3], bh0, bh1);
    mma16816(d, ah[0], ah[1], ah[2], ah[3], bl0, bl1);
    mma16816(d, al[0], al[1], al[2], al[3], bh0, bh1);
}
__device__ __forceinline__ void cpa16(void* dst, const void* src) {
    unsigned d = (unsigned)__cvta_generic_to_shared(dst);
    asm volatile("cp.async.cg.shared.global [%0], [%1], 16;\n" :: "r"(d), "l"(src));
}

// ===================== kernel 1: prep (byte-identical to passing R13) =====================
struct __align__(16) SmemP {
    float gst[CC], bst[CC], egc[CC], iegc[CC], kdec[CC], kw[CC], negbe[CC];
    __nv_bfloat16 khi[CC * KHS], klo[CC * KHS], qhi[CC * KHS], qlo[CC * KHS];
    __nv_bfloat16 abh[CC * AS2], abl[CC * AS2];
};

__global__ __launch_bounds__(NT, 2)
void gdn_prep(const float* __restrict__ gq, const float* __restrict__ gk,
              const float* __restrict__ gg, const float* __restrict__ gb) {
    extern __shared__ char smraw[];
    SmemP& sm = *reinterpret_cast<SmemP*>(smraw);
    const int tile = blockIdx.x, bh = tile / NCHUNK, n = tile % NCHUNK;
    const int b = bh / NH, h = bh % NH, s0 = n * CC;
    const int tid = threadIdx.x, warp = tid >> 5, lane = tid & 31;
    const int gq_ = lane >> 2, tig = lane & 3;
    const int lr = lane & 15, lc8 = (lane >> 4) << 3;
    const unsigned t4 = (unsigned)tile * 4096u, t2 = (unsigned)tile * 2048u;
    const float QSCALE = 0.08838834764831845f;

    if (tid < CC) {
        size_t gi = ((size_t)b * S_LEN + s0 + tid) * NH + h;
        sm.gst[tid] = gg[gi];
        sm.bst[tid] = gb[gi];
    }
    __syncthreads();
    if (warp == 0) {
        float a0 = sm.gst[lane], a1 = sm.gst[lane + 32];
#pragma unroll
        for (int o = 1; o < 32; o <<= 1) {
            float t = __shfl_up_sync(0xffffffffu, a0, o);
            if (lane >= o) a0 += t;
        }
        float tot0 = __shfl_sync(0xffffffffu, a0, 31);
#pragma unroll
        for (int o = 1; o < 32; o <<= 1) {
            float t = __shfl_up_sync(0xffffffffu, a1, o);
            if (lane >= o) a1 += t;
        }
        a1 += tot0;
        float glast = __shfl_sync(0xffffffffu, a1, 31);
        float e0 = expf(a0), e1 = expf(a1);
        sm.egc[lane] = e0;                sm.egc[lane + 32] = e1;
        sm.iegc[lane] = expf(-a0);        sm.iegc[lane + 32] = expf(-a1);
        sm.kdec[lane] = expf(glast - a0); sm.kdec[lane + 32] = expf(glast - a1);
        float b0 = sm.bst[lane], b1 = sm.bst[lane + 32];
        sm.kw[lane] = b0 * e0;            sm.kw[lane + 32] = b1 * e1;
        sm.negbe[lane] = -b0 * e0;        sm.negbe[lane + 32] = -b1 * e1;
    }
    __syncthreads();
    if (tid < CC) {
        size_t sb = (size_t)tile * 256;
        g_sc[sb + tid] = sm.kw[tid];
        g_sc[sb + 64 + tid] = sm.kdec[tid];
        g_sc[sb + 128 + tid] = sm.bst[tid];
        if (tid == 0) g_sc[sb + 192] = sm.egc[CC - 1];
    }
#pragma unroll
    for (int it = 0; it < 4; ++it)
#pragma unroll
        for (int pp = 0; pp < 2; ++pp) {
            int rr = warp + it * 16 + pp * 8;
            size_t rb = (((size_t)b * S_LEN + s0 + rr) * NH + h) * (size_t)DK + lane * 4;
            float4 qv = *(const float4*)(gq + rb);
            float4 kv = *(const float4*)(gk + rb);
            float sq = qv.x*qv.x + qv.y*qv.y + qv.z*qv.z + qv.w*qv.w;
            float sk = kv.x*kv.x + kv.y*kv.y + kv.z*kv.z + kv.w*kv.w;
#pragma unroll
            for (int o = 16; o > 0; o >>= 1) {
                sq += __shfl_xor_sync(0xffffffffu, sq, o);
                sk += __shfl_xor_sync(0xffffffffu, sk, o);
            }
            float rqs = rsqrtf(sq + 1e-6f) * QSCALE * sm.egc[rr];
            float rks = rsqrtf(sk + 1e-6f);
            int c4 = lane * 4;
            unsigned hh, ll;
            bsplit2(kv.x * rks, kv.y * rks, hh, ll);
            *(unsigned*)&sm.khi[rr*KHS + c4] = hh; *(unsigned*)&sm.klo[rr*KHS + c4] = ll;
            g_k[0][t4 + rr*64 + lane*2] = hh; g_k[1][t4 + rr*64 + lane*2] = ll;
            bsplit2(kv.z * rks, kv.w * rks, hh, ll);
            *(unsigned*)&sm.khi[rr*KHS + c4+2] = hh; *(unsigned*)&sm.klo[rr*KHS + c4+2] = ll;
            g_k[0][t4 + rr*64 + lane*2 + 1] = hh; g_k[1][t4 + rr*64 + lane*2 + 1] = ll;
            bsplit2(qv.x * rqs, qv.y * rqs, hh, ll);
            *(unsigned*)&sm.qhi[rr*KHS + c4] = hh; *(unsigned*)&sm.qlo[rr*KHS + c4] = ll;
            g_qg[0][t4 + rr*64 + lane*2] = hh; g_qg[1][t4 + rr*64 + lane*2] = ll;
            bsplit2(qv.z * rqs, qv.w * rqs, hh, ll);
            *(unsigned*)&sm.qhi[rr*KHS + c4+2] = hh; *(unsigned*)&sm.qlo[rr*KHS + c4+2] = ll;
            g_qg[0][t4 + rr*64 + lane*2 + 1] = hh; g_qg[1][t4 + rr*64 + lane*2 + 1] = ll;
        }
    __syncthreads();

    {
        const int m0 = (warp >> 1) * 16, n0 = (warp & 1) * 32;
        float accG[4][4] = {}, accQ[4][4] = {};
        if (m0 + 15 >= n0) {
            unsigned aKh = sm_addr(&sm.khi[(m0+lr)*KHS + lc8]);
            unsigned aKl = sm_addr(&sm.klo[(m0+lr)*KHS + lc8]);
            unsigned aQh = sm_addr(&sm.qhi[(m0+lr)*KHS + lc8]);
            unsigned aQl = sm_addr(&sm.qlo[(m0+lr)*KHS + lc8]);
            unsigned b0a = sm_addr(&sm.khi[(n0+lr)*KHS + lc8]);
            unsigned b0b = sm_addr(&sm.klo[(n0+lr)*KHS + lc8]);
            unsigned b1a = sm_addr(&sm.khi[(n0+16+lr)*KHS + lc8]);
            unsigned b1b = sm_addr(&sm.klo[(n0+16+lr)*KHS + lc8]);
            const bool d1 = (m0+15 >= n0+8), d2 = (m0+15 >= n0+16), d3 = (m0+15 >= n0+24);
            for (int k0 = 0; k0 < DK; k0 += 16) {
                unsigned kh[4], kl[4], qh[4], ql[4], p0h[4], p0l[4];
                ldsm4(kh, aKh + k0*2); ldsm4(kl, aKl + k0*2);
                ldsm4(qh, aQh + k0*2); ldsm4(ql, aQl + k0*2);
                ldsm4(p0h, b0a + k0*2); ldsm4(p0l, b0b + k0*2);
                mma_p3(accG[0], kh, kl, p0h[0], p0h[2], p0l[0], p0l[2]);
                mma_p3(accQ[0], qh, ql, p0h[0], p0h[2], p0l[0], p0l[2]);
                if (d1) {
                    mma_p3(accG[1], kh, kl, p0h[1], p0h[3], p0l[1], p0l[3]);
                    mma_p3(accQ[1], qh, ql, p0h[1], p0h[3], p0l[1], p0l[3]);
                }
                if (d2) {
                    unsigned p1h[4], p1l[4];
                    ldsm4(p1h, b1a + k0*2); ldsm4(p1l, b1b + k0*2);
                    mma_p3(accG[2], kh, kl, p1h[0], p1h[2], p1l[0], p1l[2]);
                    mma_p3(accQ[2], qh, ql, p1h[0], p1h[2], p1l[0], p1l[2]);
                    if (d3) {
                        mma_p3(accG[3], kh, kl, p1h[1], p1h[3], p1l[1], p1l[3]);
                        mma_p3(accQ[3], qh, ql, p1h[1], p1h[3], p1l[1], p1l[3]);
                    }
                }
            }
        }
#pragma unroll
        for (int nt = 0; nt < 4; ++nt) {
            int j0 = n0 + nt * 8 + 2 * tig;
            float ie0 = sm.iegc[j0], ie1 = sm.iegc[j0 + 1];
#pragma unroll
            for (int rh = 0; rh < 2; ++rh) {
                int i = m0 + gq_ + rh * 8;
                float nb = sm.negbe[i];
                float av0 = (i > j0)      ? nb * ie0 * accG[nt][rh*2]   : 0.f;
                float av1 = (i > j0 + 1)  ? nb * ie1 * accG[nt][rh*2+1] : 0.f;
                float at0 = (i >= j0)     ? accQ[nt][rh*2]   * ie0 : 0.f;
                float at1 = (i >= j0 + 1) ? accQ[nt][rh*2+1] * ie1 : 0.f;
                unsigned hh, ll;
                bsplit2(av0, av1, hh, ll);
                *(unsigned*)&sm.abh[i*AS2 + j0] = hh;
                *(unsigned*)&sm.abl[i*AS2 + j0] = ll;
                bsplit2(at0, at1, hh, ll);
                g_at[0][t2 + i * 32 + (j0 >> 1)] = hh;
                g_at[1][t2 + i * 32 + (j0 >> 1)] = ll;
            }
        }
    }
    __syncthreads();
    if (warp < 4) {
        const int r0 = warp * 16;
        if (lane < 16) {
            float x[16];
#pragma unroll
            for (int r = 0; r < 16; ++r) {
                float acc = (r == lane) ? 1.f : 0.f;
#pragma unroll
                for (int j = 0; j < 16; ++j)
                    if (j < r) {
                        float a = __bfloat162float(sm.abh[(r0+r)*AS2 + r0+j]) +
                                  __bfloat162float(sm.abl[(r0+r)*AS2 + r0+j]);
                        acc += a * x[j];
                    }
                x[r] = acc;
            }
            __syncwarp(0x0000ffffu);
#pragma unroll
            for (int r = 0; r < 16; ++r) {
                __nv_bfloat16 hi, lo; bsplit(x[r], hi, lo);
                sm.abh[(r0+r)*AS2 + r0 + lane] = hi;
                sm.abl[(r0+r)*AS2 + r0 + lane] = lo;
            }
        }
    } else {
        int t = (warp - 4) * 32 + lane;
        for (int w = t; w < 4096; w += 128) {
            int dk = w >> 5, c0 = (w & 31) * 2;
            float v0 = (__bfloat162float(sm.khi[c0*KHS + dk]) +
                        __bfloat162float(sm.klo[c0*KHS + dk])) * sm.kdec[c0];
            float v1 = (__bfloat162float(sm.khi[(c0+1)*KHS + dk]) +
                        __bfloat162float(sm.klo[(c0+1)*KHS + dk])) * sm.kdec[c0 + 1];
            unsigned hh, ll; bsplit2(v0, v1, hh, ll);
            g_kdT[0][t4 + w] = hh;
            g_kdT[1][t4 + w] = ll;
        }
    }
    __syncthreads();
    for (int w = tid; w < 2048; w += NT) {
        int i = w >> 5, jp = w & 31;
        g_ab[0][t2 + w] = *(unsigned*)&sm.abh[i*AS2 + 2*jp];
        g_ab[1][t2 + w] = *(unsigned*)&sm.abl[i*AS2 + 2*jp];
    }
}

// ===================== kernel 2: scan (warp-specialized) =====================
struct __align__(16) SmemS {
    float v[CC * VS];
    float vraw[CC * 32];
    float scb[2][256];
    __nv_bfloat16 khi[CC * KHS], klo[CC * KHS];
    __nv_bfloat16 qhi[CC * KHS], qlo[CC * KHS];
    __nv_bfloat16 shi[32 * KHS], slo[32 * KHS];
    __nv_bfloat16 abh[CC * AS2], abl[CC * AS2];
    __nv_bfloat16 ath[CC * AS2], atl[CC * AS2];
    __nv_bfloat16 kth[DK * KTS], ktl[DK * KTS];
    __nv_bfloat16 vth[32 * VTS], vtl[32 * VTS];
    __nv_bfloat16 rh[32 * VTS], rl[32 * VTS];
};

__global__ __launch_bounds__(NT, 1)
void gdn_scan(const float* __restrict__ gv, float* __restrict__ gout) {
    extern __shared__ char smraw[];
    SmemS& s = *reinterpret_cast<SmemS*>(smraw);
    const int bh = blockIdx.x / SPLIT, split = blockIdx.x % SPLIT;
    const int b = bh / NH, h = bh % NH;
    const int tid = threadIdx.x, warp = tid >> 5, lane = tid & 31;
    const int gq_ = lane >> 2, tig = lane & 3;
    const int lr = lane & 15, lc8 = (lane >> 4) << 3;
    const int lr2 = lane & 7, lc2 = ((lane >> 3) & 1) << 3;
    const int tile0 = bh * NCHUNK;

    const __nv_bfloat16 bz = __float2bfloat16(0.f);
    for (int i = tid; i < 32 * KHS; i += NT) { s.shi[i] = bz; s.slo[i] = bz; }

#define LD_KVS(nn, bf) do { \
    unsigned t4 = (unsigned)(tile0 + (nn)) * 4096u; \
    for (int i = tid; i < 1024; i += NT) { int r = i >> 4, j = i & 15; \
        cpa16(&s.khi[r*KHS + j*8], &g_k[0][t4 + r*64 + j*4]); \
        cpa16(&s.klo[r*KHS + j*8], &g_k[1][t4 + r*64 + j*4]); } \
    for (int i = tid; i < 512; i += NT) { int r = i >> 3, c = (i & 7) * 4; \
        cpa16(&s.vraw[r*32 + c], \
              gv + (((size_t)b * S_LEN + (nn) * CC + r) * NH + h) * (size_t)DV + \
              split * DVS + c); } \
    for (int i = tid; i < 64; i += NT) \
        cpa16(&s.scb[bf][i*4], &g_sc[(size_t)(tile0 + (nn)) * 256 + i*4]); \
    asm volatile("cp.async.commit_group;\n"); } while (0)
#define LD_AB(nn) do { \
    unsigned t2 = (unsigned)(tile0 + (nn)) * 2048u; \
    for (int i = tid; i < 512; i += NT) { int r = i >> 3, j = i & 7; \
        cpa16(&s.abh[r*AS2 + j*8], &g_ab[0][t2 + r*32 + j*4]); \
        cpa16(&s.abl[r*AS2 + j*8], &g_ab[1][t2 + r*32 + j*4]); } \
    asm volatile("cp.async.commit_group;\n"); } while (0)
#define LD_QA(nn) do { \
    unsigned t4 = (unsigned)(tile0 + (nn)) * 4096u; \
    unsigned t2 = (unsigned)(tile0 + (nn)) * 2048u; \
    for (int i = tid; i < 1024; i += NT) { int r = i >> 4, j = i & 15; \
        cpa16(&s.qhi[r*KHS + j*8], &g_qg[0][t4 + r*64 + j*4]); \
        cpa16(&s.qlo[r*KHS + j*8], &g_qg[1][t4 + r*64 + j*4]); } \
    for (int i = tid; i < 512; i += NT) { int r = i >> 3, j = i & 7; \
        cpa16(&s.ath[r*AS2 + j*8], &g_at[0][t2 + r*32 + j*4]); \
        cpa16(&s.atl[r*AS2 + j*8], &g_at[1][t2 + r*32 + j*4]); } \
    for (int i = tid; i < 1024; i += NT) { int r = i >> 3, j = i & 7; \
        cpa16(&s.kth[r*KTS + j*8], &g_kdT[0][t4 + r*32 + j*4]); \
        cpa16(&s.ktl[r*KTS + j*8], &g_kdT[1][t4 + r*32 + j*4]); } \
    asm volatile("cp.async.commit_group;\n"); } while (0)

    LD_KVS(0, 0); LD_AB(0); LD_QA(0);

    for (int n = 0; n < NCHUNK; ++n) {
        const int cur = n & 1, s0 = n * CC;
        const int nn1 = (n + 1 < NCHUNK) ? n + 1 : n;
        asm volatile("cp.async.wait_group 2;\n");       // KVS(n)
        __syncthreads();
        const float* sc = s.scb[cur];

        // P2: rhs = vraw*beta - kw*(K@S); warps 0,1 write rh/rl (block0) direct
        {
            const int m0 = (warp & 1) * 16, n0 = (warp >> 1) * 16;
            float acc[2][4] = {};
            unsigned aSh = sm_addr(&s.shi[(m0+lr)*KHS + lc8]);
            unsigned aSl = sm_addr(&s.slo[(m0+lr)*KHS + lc8]);
            unsigned bKh = sm_addr(&s.khi[(n0+lr)*KHS + lc8]);
            unsigned bKl = sm_addr(&s.klo[(n0+lr)*KHS + lc8]);
            for (int k0 = 0; k0 < DK; k0 += 16) {
                unsigned ah[4], al[4], bh4[4], bl4[4];
                ldsm4(ah, aSh + k0*2); ldsm4(al, aSl + k0*2);
                ldsm4(bh4, bKh + k0*2); ldsm4(bl4, bKl + k0*2);
                mma_p3(acc[0], ah, al, bh4[0], bh4[2], bl4[0], bl4[2]);
                mma_p3(acc[1], ah, al, bh4[1], bh4[3], bl4[1], bl4[3]);
            }
#pragma unroll
            for (int nt = 0; nt < 2; ++nt)
#pragma unroll
                for (int rh2 = 0; rh2 < 2; ++rh2) {
                    int i = m0 + gq_ + rh2 * 8;
                    int j0 = n0 + nt * 8 + 2 * tig;
                    float vb0 = s.vraw[j0*32 + i] * sc[128 + j0]
                                - sc[j0] * acc[nt][rh2*2];
                    float vb1 = s.vraw[(j0+1)*32 + i] * sc[128 + j0 + 1]
                                - sc[j0 + 1] * acc[nt][rh2*2 + 1];
                    if (n0 == 0) {
                        unsigned hh, ll; bsplit2(vb0, vb1, hh, ll);
                        *(unsigned*)&s.rh[i*VTS + j0] = hh;
                        *(unsigned*)&s.rl[i*VTS + j0] = ll;
                    } else {
                        s.v[j0 * VS + i] = vb0;
                        s.v[(j0 + 1) * VS + i] = vb1;
                    }
                }
        }
        __syncthreads();
        LD_KVS(nn1, cur ^ 1);
        asm volatile("cp.async.wait_group 1;\n");       // AB(n) + QA(n)
        __syncthreads();

        // ---- solve (warps 0-3, per-warp) || P4-inter S@qg^T (warps 4-7) ----
        float accP4[4][4] = {};
        if (warp < 4) {
            const int n0 = warp * 8;
#pragma unroll
            for (int blk = 0; blk < 4; ++blk) {
                const int i0 = blk * 16;
                if (blk > 0) {
                    float acc[4] = {0, 0, 0, 0};
                    unsigned aAh = sm_addr(&s.abh[(i0+lr)*AS2 + lc8]);
                    unsigned aAl = sm_addr(&s.abl[(i0+lr)*AS2 + lc8]);
                    unsigned bVh = sm_addr(&s.vth[(n0+lr2)*VTS + lc2]);
                    unsigned bVl = sm_addr(&s.vtl[(n0+lr2)*VTS + lc2]);
                    for (int ks = 0; ks < blk; ++ks) {
                        unsigned ah[4], al[4], bh2[2], bl2[2];
                        ldsm4(ah, aAh + ks*32); ldsm4(al, aAl + ks*32);
                        ldsm2(bh2, bVh + ks*32); ldsm2(bl2, bVl + ks*32);
                        mma_p3(acc, ah, al, bh2[0], bh2[1], bl2[0], bl2[1]);
                    }
#pragma unroll
                    for (int e = 0; e < 4; ++e) {
                        int i = i0 + gq_ + ((e >> 1) << 3);
                        int dv = n0 + 2 * tig + (e & 1);
                        float r = s.v[i * VS + dv] + acc[e];
                        __nv_bfloat16 hi, lo; bsplit(r, hi, lo);
                        s.rh[dv * VTS + (i - i0)] = hi;
                        s.rl[dv * VTS + (i - i0)] = lo;
                    }
                    __syncwarp();
                }
                {
                    unsigned ah[4], al[4], bh2[2], bl2[2];
                    ldsm4(ah, sm_addr(&s.abh[(i0+lr)*AS2 + i0 + lc8]));
                    ldsm4(al, sm_addr(&s.abl[(i0+lr)*AS2 + i0 + lc8]));
                    ldsm2(bh2, sm_addr(&s.rh[(n0+lr2)*VTS + lc2]));
                    ldsm2(bl2, sm_addr(&s.rl[(n0+lr2)*VTS + lc2]));
                    float acc[4] = {0, 0, 0, 0};
                    mma_p3(acc, ah, al, bh2[0], bh2[1], bl2[0], bl2[1]);
#pragma unroll
                    for (int e = 0; e < 4; ++e) {
                        int i = i0 + gq_ + ((e >> 1) << 3);
                        int dv = n0 + 2 * tig + (e & 1);
                        s.v[i * VS + dv] = acc[e];
                        __nv_bfloat16 hi, lo; bsplit(acc[e], hi, lo);
                        s.vth[dv * VTS + i] = hi;
                        s.vtl[dv * VTS + i] = lo;
                    }
                    __syncwarp();
                }
            }
        } else {
            const int wp = warp - 4;
            const int m0 = (wp & 1) * 16, n0q = (wp >> 1) * 32;
            unsigned aSh = sm_addr(&s.shi[(m0+lr)*KHS + lc8]);
            unsigned aSl = sm_addr(&s.slo[(m0+lr)*KHS + lc8]);
            unsigned b0a = sm_addr(&s.qhi[(n0q+lr)*KHS + lc8]);
            unsigned b0b = sm_addr(&s.qlo[(n0q+lr)*KHS + lc8]);
            unsigned b1a = sm_addr(&s.qhi[(n0q+16+lr)*KHS + lc8]);
            unsigned b1b = sm_addr(&s.qlo[(n0q+16+lr)*KHS + lc8]);
            for (int k0 = 0; k0 < DK; k0 += 16) {
                unsigned ah[4], al[4], p0h[4], p0l[4], p1h[4], p1l[4];
                ldsm4(ah, aSh + k0*2); ldsm4(al, aSl + k0*2);
                ldsm4(p0h, b0a + k0*2); ldsm4(p0l, b0b + k0*2);
                ldsm4(p1h, b1a + k0*2); ldsm4(p1l, b1b + k0*2);
                mma_p3(accP4[0], ah, al, p0h[0], p0h[2], p0l[0], p0l[2]);
                mma_p3(accP4[1], ah, al, p0h[1], p0h[3], p0l[1], p0l[3]);
                mma_p3(accP4[2], ah, al, p1h[0], p1h[2], p1l[0], p1l[2]);
                mma_p3(accP4[3], ah, al, p1h[1], p1h[3], p1l[1], p1l[3]);
            }
        }
        __syncthreads();      // vth complete; abh free
        LD_AB(nn1);

        // ---- split phase: warps 4-7 finish P4+store || warps 0-3 P5+RMW ----
        if (warp >= 4) {
            const int wp = warp - 4;
            const int m0 = (wp & 1) * 16, n0q = (wp >> 1) * 32;
            unsigned aVh = sm_addr(&s.vth[(m0+lr)*VTS + lc8]);
            unsigned aVl = sm_addr(&s.vtl[(m0+lr)*VTS + lc8]);
            unsigned c0a = sm_addr(&s.ath[(n0q+lr)*AS2 + lc8]);
            unsigned c0b = sm_addr(&s.atl[(n0q+lr)*AS2 + lc8]);
            unsigned c1a = sm_addr(&s.ath[(n0q+16+lr)*AS2 + lc8]);
            unsigned c1b = sm_addr(&s.atl[(n0q+16+lr)*AS2 + lc8]);
            for (int k0 = 0; k0 < CC; k0 += 16) {
                unsigned ah[4], al[4], p0h[4], p0l[4], p1h[4], p1l[4];
                ldsm4(ah, aVh + k0*2); ldsm4(al, aVl + k0*2);
                ldsm4(p0h, c0a + k0*2); ldsm4(p0l, c0b + k0*2);
                ldsm4(p1h, c1a + k0*2); ldsm4(p1l, c1b + k0*2);
                mma_p3(accP4[0], ah, al, p0h[0], p0h[2], p0l[0], p0l[2]);
                mma_p3(accP4[1], ah, al, p0h[1], p0h[3], p0l[1], p0l[3]);
                mma_p3(accP4[2], ah, al, p1h[0], p1h[2], p1l[0], p1l[2]);
                mma_p3(accP4[3], ah, al, p1h[1], p1h[3], p1l[1], p1l[3]);
            }
#pragma unroll
            for (int nt = 0; nt < 4; ++nt)
#pragma unroll
                for (int e = 0; e < 4; ++e) {
                    int dv = m0 + gq_ + ((e >> 1) << 3);
                    int c = n0q + nt * 8 + 2 * tig + (e & 1);
                    gout[(((size_t)b * S_LEN + s0 + c) * NH + h) * (size_t)DV +
                         split * DVS + dv] = accP4[nt][e];
                }
        } else {
            const int m0 = (warp & 1) * 16, nn0 = (warp >> 1) * 64;
            float acc5[8][4] = {};
            unsigned aVh = sm_addr(&s.vth[(m0+lr)*VTS + lc8]);
            unsigned aVl = sm_addr(&s.vtl[(m0+lr)*VTS + lc8]);
            for (int k0 = 0; k0 < CC; k0 += 16) {
                unsigned ah[4], al[4];
                ldsm4(ah, aVh + k0*2); ldsm4(al, aVl + k0*2);
#pragma unroll
                for (int p = 0; p < 4; ++p) {
                    unsigned pbh[4], pbl[4];
                    ldsm4(pbh, sm_addr(&s.kth[(nn0 + p*16 + lr)*KTS + lc8]) + k0*2);
                    ldsm4(pbl, sm_addr(&s.ktl[(nn0 + p*16 + lr)*KTS + lc8]) + k0*2);
                    mma_p3(acc5[2*p],   ah, al, pbh[0], pbh[2], pbl[0], pbl[2]);
                    mma_p3(acc5[2*p+1], ah, al, pbh[1], pbh[3], pbl[1], pbl[3]);
                }
            }
            float egl = sc[192];
#pragma unroll
            for (int nt = 0; nt < 8; ++nt)
#pragma unroll
                for (int rh2 = 0; rh2 < 2; ++rh2) {
                    int dv = m0 + gq_ + rh2 * 8, dk0 = nn0 + nt * 8 + 2 * tig;
                    float2 so = upk(*(unsigned*)&s.shi[dv*KHS + dk0],
                                    *(unsigned*)&s.slo[dv*KHS + dk0]);
                    unsigned hh, ll;
                    bsplit2(so.x * egl + acc5[nt][rh2*2],
                            so.y * egl + acc5[nt][rh2*2+1], hh, ll);
                    *(unsigned*)&s.shi[dv*KHS + dk0] = hh;
                    *(unsigned*)&s.slo[dv*KHS + dk0] = ll;
                }
        }
        __syncthreads();
        LD_QA(nn1);
    }
}

extern "C" void kernel_launch(void* const* d_in, const int* in_sizes, int n_in,
                              void* d_out, int out_size) {
    const float* q = (const float*)d_in[0];
    const float* k = (const float*)d_in[1];
    const float* v = (const float*)d_in[2];
    const float* g = (const float*)d_in[3];
    const float* beta = (const float*)d_in[4];
    float* out = (float*)d_out;
    int B = in_sizes[0] / (S_LEN * NH * DK);
    if (B < 1) B = 1;
    cudaFuncSetAttribute(gdn_prep, cudaFuncAttributeMaxDynamicSharedMemorySize,
                         (int)sizeof(SmemP));
    cudaFuncSetAttribute(gdn_scan, cudaFuncAttributeMaxDynamicSharedMemorySize,
                         (int)sizeof(SmemS));
    gdn_prep<<<B * NH * NCHUNK, NT, sizeof(SmemP)>>>(q, k, g, beta);
    gdn_scan<<<B * NH * SPLIT, NT, sizeof(SmemS)>>>(v, out);
}